// round 5
// baseline (speedup 1.0000x reference)
#include <cuda_runtime.h>
#include <cuda_bf16.h>
#include <cstdint>

// Problem constants
#define Bb   2
#define Tt   2048
#define Cc   2048
#define Hh   16
#define KVH_ 4
#define HD_  128
#define BT   (Bb*Tt)          // 4096
#define REP  (Hh/KVH_)        // 4

// Scratch buffers (device globals: allocation-free rule).
__device__ float g_q[BT * Hh * HD_];      // (B,T,H,HD)  32MB
__device__ float g_k[BT * KVH_ * HD_];    // (B,T,KVH,HD) 8MB
__device__ float g_v[BT * KVH_ * HD_];    // 8MB
__device__ float g_y[BT * Cc];            // 32MB

// ---------------------------------------------------------------------------
// SGEMM: C[M,N] = A[M,K] @ B[K,N], row-major fp32.
// 128x128 block tile, BK=16, 256 threads, 8x8 per thread (split 4+4 layout).
// ASRC: 0 = external A, 1 = g_y.   DST: 0=g_q, 1=g_k, 2=g_v, 3=external C.
// (Device-symbol addresses are resolved in DEVICE code only.)
// ---------------------------------------------------------------------------
template<int ASRC, int DST>
__global__ void __launch_bounds__(256) sgemm_kernel(
    const float* __restrict__ Aext, const float* __restrict__ B,
    float* __restrict__ Cext, int M, int N, int K)
{
    const float* A = (ASRC == 0) ? Aext : (const float*)g_y;
    float* C;
    if      (DST == 0) C = g_q;
    else if (DST == 1) C = g_k;
    else if (DST == 2) C = g_v;
    else               C = Cext;

    __shared__ float As[16][132];   // transposed A tile (padded)
    __shared__ float Bs[16][128];

    const int tid = threadIdx.x;
    const int tx = tid & 15, ty = tid >> 4;
    const int bm = blockIdx.y * 128, bn = blockIdx.x * 128;

    const int r0 = ty * 4, r1 = 64 + ty * 4;
    const int c0 = tx * 4, c1 = 64 + tx * 4;

    float acc[8][8];
#pragma unroll
    for (int i = 0; i < 8; i++)
#pragma unroll
        for (int j = 0; j < 8; j++) acc[i][j] = 0.0f;

    for (int k0 = 0; k0 < K; k0 += 16) {
#pragma unroll
        for (int f = tid; f < 512; f += 256) {
            int m  = f >> 2;
            int kc = (f & 3) * 4;
            float4 av = *(const float4*)(A + (size_t)(bm + m) * K + k0 + kc);
            As[kc + 0][m] = av.x;
            As[kc + 1][m] = av.y;
            As[kc + 2][m] = av.z;
            As[kc + 3][m] = av.w;
        }
#pragma unroll
        for (int f = tid; f < 512; f += 256) {
            int kr = f >> 5;
            int c  = (f & 31) * 4;
            *(float4*)(&Bs[kr][c]) = *(const float4*)(B + (size_t)(k0 + kr) * N + bn + c);
        }
        __syncthreads();

#pragma unroll
        for (int kk = 0; kk < 16; kk++) {
            float4 a0 = *(float4*)(&As[kk][r0]);
            float4 a1 = *(float4*)(&As[kk][r1]);
            float4 b0 = *(float4*)(&Bs[kk][c0]);
            float4 b1 = *(float4*)(&Bs[kk][c1]);
#pragma unroll
            for (int i = 0; i < 8; i++) {
                float av = (i==0)?a0.x:(i==1)?a0.y:(i==2)?a0.z:(i==3)?a0.w:
                           (i==4)?a1.x:(i==5)?a1.y:(i==6)?a1.z:a1.w;
                acc[i][0] = fmaf(av, b0.x, acc[i][0]);
                acc[i][1] = fmaf(av, b0.y, acc[i][1]);
                acc[i][2] = fmaf(av, b0.z, acc[i][2]);
                acc[i][3] = fmaf(av, b0.w, acc[i][3]);
                acc[i][4] = fmaf(av, b1.x, acc[i][4]);
                acc[i][5] = fmaf(av, b1.y, acc[i][5]);
                acc[i][6] = fmaf(av, b1.z, acc[i][6]);
                acc[i][7] = fmaf(av, b1.w, acc[i][7]);
            }
        }
        __syncthreads();
    }

#pragma unroll
    for (int i = 0; i < 8; i++) {
        int row = bm + ((i < 4) ? (r0 + i) : (r1 + i - 4));
        float4 v0 = make_float4(acc[i][0], acc[i][1], acc[i][2], acc[i][3]);
        float4 v1 = make_float4(acc[i][4], acc[i][5], acc[i][6], acc[i][7]);
        *(float4*)(C + (size_t)row * N + bn + c0) = v0;
        *(float4*)(C + (size_t)row * N + bn + c1) = v1;
    }
}

// ---------------------------------------------------------------------------
// RoPE + RMSNorm, one warp per (b,t,head) row of 128.
// ---------------------------------------------------------------------------
__global__ void rope_rmsnorm_kernel(const float* __restrict__ cosp,
                                    const float* __restrict__ sinp,
                                    const float* __restrict__ qk_w)
{
    const int QROWS = BT * Hh;        // 65536
    const int KROWS = BT * KVH_;      // 16384
    int warp = (blockIdx.x * blockDim.x + threadIdx.x) >> 5;
    int lane = threadIdx.x & 31;
    float* row;
    int t;
    if (warp < QROWS) {
        t = (warp / Hh) % Tt;
        row = g_q + (size_t)warp * HD_;
    } else {
        int w = warp - QROWS;
        if (w >= KROWS) return;
        t = (w / KVH_) % Tt;
        row = g_k + (size_t)w * HD_;
    }
    int j0 = lane, j1 = lane + 32;
    float x1a = row[j0],      x1b = row[j1];
    float x2a = row[j0 + 64], x2b = row[j1 + 64];
    float ca = cosp[t * 64 + j0], sa = sinp[t * 64 + j0];
    float cb = cosp[t * 64 + j1], sb = sinp[t * 64 + j1];
    float o1a = x1a * ca - x2a * sa, o2a = x2a * ca + x1a * sa;
    float o1b = x1b * cb - x2b * sb, o2b = x2b * cb + x1b * sb;
    float ss = o1a * o1a + o2a * o2a + o1b * o1b + o2b * o2b;
#pragma unroll
    for (int off = 16; off; off >>= 1) ss += __shfl_xor_sync(0xffffffffu, ss, off);
    float rms = rsqrtf(ss * (1.0f / 128.0f) + 1e-6f);
    row[j0]      = o1a * rms * qk_w[j0];
    row[j1]      = o1b * rms * qk_w[j1];
    row[j0 + 64] = o2a * rms * qk_w[j0 + 64];
    row[j1 + 64] = o2b * rms * qk_w[j1 + 64];
}

// ---------------------------------------------------------------------------
// Flash attention, fp32, causal, GQA. BM=128, BN=64, D=128, 256 threads.
// Per-thread: S tile 8x4 (32 regs), O tile 8x8 (64 regs) -> no spills.
// Smem: Qst[128][132] (d-major, transposed), Kst[128][68] (d-major),
//       Pst[64][132] (P^T), Vs[64][128].
// ---------------------------------------------------------------------------
#define QPAD 132
#define KPAD 68
#define FA_SMEM_FLOATS (128*QPAD + 128*KPAD + 64*QPAD + 64*128)

__global__ void __launch_bounds__(256, 1) flash_attn_kernel()
{
    extern __shared__ float smem[];
    float* Qst = smem;                          // [d][m] 128 x 132
    float* Kst = Qst + 128 * QPAD;              // [d][n] 128 x 68
    float* Pst = Kst + 128 * KPAD;              // [n][m] 64 x 132
    float* Vs  = Pst + 64 * QPAD;               // [n][d] 64 x 128

    const int qi = blockIdx.x, h = blockIdx.y, b = blockIdx.z;
    const int kvh = h / REP;
    const int tid = threadIdx.x;
    const int tx = tid & 15, ty = tid >> 4;
    const int r0 = ty * 4, r1 = 64 + ty * 4;    // 8 rows per thread
    const int cS = tx * 4;                      // 4 S-cols per thread
    const int c0 = tx * 4, c1 = 64 + tx * 4;    // 8 O-cols per thread
    const float scale = 0.08838834764831845f;   // 1/sqrt(128)

    const int qbase = qi * 128;
    const float* qptr = g_q + (((size_t)b * Tt + qbase) * Hh + h) * HD_;

    // load Q tile transposed + pre-scaled
    for (int f = tid; f < 128 * 32; f += 256) {
        int m  = f >> 5;
        int d4 = (f & 31) * 4;
        float4 val = *(const float4*)(qptr + (size_t)m * Hh * HD_ + d4);
        Qst[(d4 + 0) * QPAD + m] = val.x * scale;
        Qst[(d4 + 1) * QPAD + m] = val.y * scale;
        Qst[(d4 + 2) * QPAD + m] = val.z * scale;
        Qst[(d4 + 3) * QPAD + m] = val.w * scale;
    }

    float o[8][8];
    float mrow[8], lrow[8];
#pragma unroll
    for (int i = 0; i < 8; i++) {
        mrow[i] = -3.0e38f; lrow[i] = 0.0f;
#pragma unroll
        for (int j = 0; j < 8; j++) o[i][j] = 0.0f;
    }

    const int ntiles = 2 * (qi + 1);            // 64-wide KV tiles
    for (int nt = 0; nt < ntiles; nt++) {
        const int kbase = nt * 64;
        __syncthreads();   // protects Qst (iter 0) and Pst/Vs from prior iter
        const float* kptr = g_k + (((size_t)b * Tt + kbase) * KVH_ + kvh) * HD_;
        const float* vptr = g_v + (((size_t)b * Tt + kbase) * KVH_ + kvh) * HD_;
        // 64 rows x 128 d, float4: 2048 chunks / 256 threads = 8 each
        for (int f = tid; f < 64 * 32; f += 256) {
            int n  = f >> 5;
            int d4 = (f & 31) * 4;
            float4 kv = *(const float4*)(kptr + (size_t)n * KVH_ * HD_ + d4);
            Kst[(d4 + 0) * KPAD + n] = kv.x;
            Kst[(d4 + 1) * KPAD + n] = kv.y;
            Kst[(d4 + 2) * KPAD + n] = kv.z;
            Kst[(d4 + 3) * KPAD + n] = kv.w;
            float4 vv = *(const float4*)(vptr + (size_t)n * KVH_ * HD_ + d4);
            *(float4*)(Vs + n * 128 + d4) = vv;
        }
        __syncthreads();

        // ---- S = (Q*scale) @ K^T : per-thread 8 x 4 ----
        float s[8][4];
#pragma unroll
        for (int i = 0; i < 8; i++)
#pragma unroll
            for (int j = 0; j < 4; j++) s[i][j] = 0.0f;

#pragma unroll 4
        for (int kk = 0; kk < 128; kk++) {
            float4 a0 = *(float4*)(Qst + kk * QPAD + r0);
            float4 a1 = *(float4*)(Qst + kk * QPAD + r1);
            float4 bv = *(float4*)(Kst + kk * KPAD + cS);
#pragma unroll
            for (int i = 0; i < 8; i++) {
                float av = (i==0)?a0.x:(i==1)?a0.y:(i==2)?a0.z:(i==3)?a0.w:
                           (i==4)?a1.x:(i==5)?a1.y:(i==6)?a1.z:a1.w;
                s[i][0] = fmaf(av, bv.x, s[i][0]);
                s[i][1] = fmaf(av, bv.y, s[i][1]);
                s[i][2] = fmaf(av, bv.z, s[i][2]);
                s[i][3] = fmaf(av, bv.w, s[i][3]);
            }
        }

        // causal mask (tiles overlapping the diagonal)
        if (kbase + 63 > qbase) {
#pragma unroll
            for (int i = 0; i < 8; i++) {
                int rg = qbase + ((i < 4) ? (r0 + i) : (r1 + i - 4));
#pragma unroll
                for (int j = 0; j < 4; j++) {
                    int cg = kbase + cS + j;
                    if (cg > rg) s[i][j] = -3.0e38f;
                }
            }
        }

        // ---- online softmax (row = 16 threads across tx, width-16 shfl) ----
#pragma unroll
        for (int i = 0; i < 8; i++) {
            float mx = fmaxf(fmaxf(s[i][0], s[i][1]), fmaxf(s[i][2], s[i][3]));
#pragma unroll
            for (int off = 8; off >= 1; off >>= 1)
                mx = fmaxf(mx, __shfl_xor_sync(0xffffffffu, mx, off, 16));
            float mnew = fmaxf(mrow[i], mx);
            float corr = __expf(mrow[i] - mnew);
            mrow[i] = mnew;
            float ls = 0.0f;
#pragma unroll
            for (int j = 0; j < 4; j++) {
                s[i][j] = __expf(s[i][j] - mnew);
                ls += s[i][j];
            }
#pragma unroll
            for (int off = 8; off >= 1; off >>= 1)
                ls += __shfl_xor_sync(0xffffffffu, ls, off, 16);
            lrow[i] = lrow[i] * corr + ls;
#pragma unroll
            for (int j = 0; j < 8; j++) o[i][j] *= corr;
        }

        // store P transposed: Pst[n][m]
#pragma unroll
        for (int i = 0; i < 8; i++) {
            int rm = (i < 4) ? (r0 + i) : (r1 + i - 4);
#pragma unroll
            for (int j = 0; j < 4; j++)
                Pst[(cS + j) * QPAD + rm] = s[i][j];
        }
        __syncthreads();

        // ---- O += P @ V ----
#pragma unroll 4
        for (int n = 0; n < 64; n++) {
            float4 p0 = *(float4*)(Pst + n * QPAD + r0);
            float4 p1 = *(float4*)(Pst + n * QPAD + r1);
            float4 v0 = *(float4*)(Vs + n * 128 + c0);
            float4 v1 = *(float4*)(Vs + n * 128 + c1);
#pragma unroll
            for (int i = 0; i < 8; i++) {
                float pv = (i==0)?p0.x:(i==1)?p0.y:(i==2)?p0.z:(i==3)?p0.w:
                           (i==4)?p1.x:(i==5)?p1.y:(i==6)?p1.z:p1.w;
                o[i][0] = fmaf(pv, v0.x, o[i][0]);
                o[i][1] = fmaf(pv, v0.y, o[i][1]);
                o[i][2] = fmaf(pv, v0.z, o[i][2]);
                o[i][3] = fmaf(pv, v0.w, o[i][3]);
                o[i][4] = fmaf(pv, v1.x, o[i][4]);
                o[i][5] = fmaf(pv, v1.y, o[i][5]);
                o[i][6] = fmaf(pv, v1.z, o[i][6]);
                o[i][7] = fmaf(pv, v1.w, o[i][7]);
            }
        }
    }

    // epilogue: O /= l, write to g_y (B,T,C) at column h*HD + d
#pragma unroll
    for (int i = 0; i < 8; i++) {
        int rm = (i < 4) ? (r0 + i) : (r1 + i - 4);
        float inv = 1.0f / lrow[i];
        size_t base = (((size_t)b * Tt + qbase + rm) * Cc) + (size_t)h * HD_;
        float4 v0 = make_float4(o[i][0] * inv, o[i][1] * inv, o[i][2] * inv, o[i][3] * inv);
        float4 v1 = make_float4(o[i][4] * inv, o[i][5] * inv, o[i][6] * inv, o[i][7] * inv);
        *(float4*)(g_y + base + c0) = v0;
        *(float4*)(g_y + base + c1) = v1;
    }
}

// ---------------------------------------------------------------------------
// Launch
// ---------------------------------------------------------------------------
extern "C" void kernel_launch(void* const* d_in, const int* in_sizes, int n_in,
                              void* d_out, int out_size)
{
    const float* x    = (const float*)d_in[0];
    const float* cosp = (const float*)d_in[1];
    const float* sinp = (const float*)d_in[2];
    const float* wq   = (const float*)d_in[3];
    const float* wk   = (const float*)d_in[4];
    const float* wv   = (const float*)d_in[5];
    const float* wo   = (const float*)d_in[6];
    const float* qkw  = (const float*)d_in[7];
    float* out = (float*)d_out;

    // QKV projections
    sgemm_kernel<0,0><<<dim3(Cc / 128, BT / 128), 256>>>(x, wq, nullptr, BT, Cc, Cc);
    sgemm_kernel<0,1><<<dim3((KVH_ * HD_) / 128, BT / 128), 256>>>(x, wk, nullptr, BT, KVH_ * HD_, Cc);
    sgemm_kernel<0,2><<<dim3((KVH_ * HD_) / 128, BT / 128), 256>>>(x, wv, nullptr, BT, KVH_ * HD_, Cc);

    // RoPE + RMSNorm on q and k
    {
        int total_warps = BT * Hh + BT * KVH_;   // 81920
        int threads = 256;
        int blocks = (total_warps * 32 + threads - 1) / threads;
        rope_rmsnorm_kernel<<<blocks, threads>>>(cosp, sinp, qkw);
    }

    // flash attention (~169 KB dynamic smem)
    {
        size_t smem_bytes = FA_SMEM_FLOATS * sizeof(float);
        cudaFuncSetAttribute(flash_attn_kernel,
                             cudaFuncAttributeMaxDynamicSharedMemorySize,
                             (int)smem_bytes);
        flash_attn_kernel<<<dim3(Tt / 128, Hh, Bb), 256, smem_bytes>>>();
    }

    // output projection: A = g_y (resolved device-side), C = out
    sgemm_kernel<1,3><<<dim3(Cc / 128, BT / 128), 256>>>(nullptr, wo, out, BT, Cc, Cc);
}

// round 7
// speedup vs baseline: 1.7630x; 1.7630x over previous
#include <cuda_runtime.h>
#include <cuda_bf16.h>
#include <cstdint>

// Problem constants
#define Bb   2
#define Tt   2048
#define Cc   2048
#define Hh   16
#define KVH_ 4
#define HD_  128
#define BT   (Bb*Tt)          // 4096
#define REP  (Hh/KVH_)        // 4

// Scratch buffers (device globals: allocation-free rule).
__device__ float g_q[BT * Hh * HD_];      // (B,T,H,HD)  32MB
__device__ float g_k[BT * KVH_ * HD_];    // (B,T,KVH,HD) 8MB
__device__ float g_v[BT * KVH_ * HD_];    // 8MB
__device__ float g_y[BT * Cc];            // 32MB (tf32-rounded by FA epilogue)
// tf32-rounded copies of GEMM inputs
__device__ float g_xr[BT * Cc];           // 32MB
__device__ float g_wq_r[Cc * Cc];         // 16MB
__device__ float g_wk_r[Cc * KVH_ * HD_]; // 4MB
__device__ float g_wv_r[Cc * KVH_ * HD_]; // 4MB
__device__ float g_wo_r[Cc * Cc];         // 16MB

__device__ __forceinline__ float to_tf32(float v) {
    unsigned r;
    asm("cvt.rna.tf32.f32 %0, %1;" : "=r"(r) : "f"(v));
    return __uint_as_float(r);
}

// ---------------------------------------------------------------------------
// Pre-pass: round inputs to tf32 (round-to-nearest; avoids truncation bias).
// R: 0=x->g_xr, 1=wq, 2=wk, 3=wv, 4=wo
// ---------------------------------------------------------------------------
template<int R>
__global__ void round_kernel(const float* __restrict__ src, int n4)
{
    float* dst;
    if      (R == 0) dst = g_xr;
    else if (R == 1) dst = g_wq_r;
    else if (R == 2) dst = g_wk_r;
    else if (R == 3) dst = g_wv_r;
    else             dst = g_wo_r;
    int i = blockIdx.x * blockDim.x + threadIdx.x;
    if (i >= n4) return;
    float4 v = ((const float4*)src)[i];
    v.x = to_tf32(v.x); v.y = to_tf32(v.y);
    v.z = to_tf32(v.z); v.w = to_tf32(v.w);
    ((float4*)dst)[i] = v;
}

// ---------------------------------------------------------------------------
// tf32 tensor-core GEMM: C[M,N] = A[M,K] @ B[K,N], row-major.
// Tile 128x128, BK=32, 256 threads (2x4 warps, 64x32 per warp),
// mma.sync.m16n8k8.tf32, cp.async double-buffered.
// OP: 0=q (A=g_xr,B=g_wq_r,C=g_q,N=2048), 1=k (N=512), 2=v (N=512),
//     3=out (A=g_y, B=g_wo_r, C=Cext, N=2048).  M=4096, K=2048 always.
// ---------------------------------------------------------------------------
#define GK 2048
#define GM 4096
#define APITCH 36     // smem A row pitch (floats)
#define BPITCH 136    // smem B row pitch (floats)
#define ABUF (128 * APITCH)     // 4608 floats
#define BBUF (32 * BPITCH)      // 4352 floats
#define GEMM_SMEM_FLOATS (2 * (ABUF + BBUF))   // 17920 floats = 71680 B

__device__ __forceinline__ void cp_async16(uint32_t smem_addr, const void* gptr) {
    asm volatile("cp.async.cg.shared.global [%0], [%1], 16;\n"
                 :: "r"(smem_addr), "l"(gptr));
}
__device__ __forceinline__ void cp_commit() {
    asm volatile("cp.async.commit_group;\n");
}
template<int N>
__device__ __forceinline__ void cp_wait() {
    asm volatile("cp.async.wait_group %0;\n" :: "n"(N));
}

__device__ __forceinline__ void mma_tf32(
    float& d0, float& d1, float& d2, float& d3,
    uint32_t a0, uint32_t a1, uint32_t a2, uint32_t a3,
    uint32_t b0, uint32_t b1)
{
    asm volatile(
        "mma.sync.aligned.m16n8k8.row.col.f32.tf32.tf32.f32 "
        "{%0,%1,%2,%3}, {%4,%5,%6,%7}, {%8,%9}, {%0,%1,%2,%3};\n"
        : "+f"(d0), "+f"(d1), "+f"(d2), "+f"(d3)
        : "r"(a0), "r"(a1), "r"(a2), "r"(a3), "r"(b0), "r"(b1));
}

template<int OP>
__global__ void __launch_bounds__(256) tf32_gemm(float* __restrict__ Cext)
{
    constexpr int N = (OP == 1 || OP == 2) ? (KVH_ * HD_) : Cc;
    const float* A = (OP == 3) ? g_y : g_xr;
    const float* B;
    if      (OP == 0) B = g_wq_r;
    else if (OP == 1) B = g_wk_r;
    else if (OP == 2) B = g_wv_r;
    else              B = g_wo_r;
    float* C;
    if      (OP == 0) C = g_q;
    else if (OP == 1) C = g_k;
    else if (OP == 2) C = g_v;
    else              C = Cext;

    extern __shared__ float sm[];
    float* As = sm;                 // [2][128][APITCH]
    float* Bs = sm + 2 * ABUF;      // [2][32][BPITCH]

    const int tid  = threadIdx.x;
    const int wid  = tid >> 5;
    const int lane = tid & 31;
    const int gid  = lane >> 2;     // 0..7
    const int tig  = lane & 3;      // 0..3
    const int mbase = (wid >> 2) * 64;   // warp M offset (0 or 64)
    const int nbase = (wid & 3) * 32;    // warp N offset (0,32,64,96)
    const int bm = blockIdx.y * 128, bn = blockIdx.x * 128;

    // accumulators: 4 m-tiles x 4 n-tiles x 4 regs
    float d[4][4][4];
#pragma unroll
    for (int i = 0; i < 4; i++)
#pragma unroll
        for (int j = 0; j < 4; j++)
#pragma unroll
            for (int r = 0; r < 4; r++) d[i][j][r] = 0.0f;

    uint32_t sbase = (uint32_t)__cvta_generic_to_shared(sm);

    // stage loader: 4 A chunks + 4 B chunks of 16B per thread
    auto issue_stage = [&](int k0, int buf) {
#pragma unroll
        for (int i = 0; i < 4; i++) {
            int f   = tid + i * 256;          // 0..1023
            int row = f >> 3;                 // 0..127
            int kc  = (f & 7) * 4;            // 0..28
            uint32_t daddr = sbase + (uint32_t)((buf * ABUF + row * APITCH + kc) * 4);
            cp_async16(daddr, A + (size_t)(bm + row) * GK + k0 + kc);
        }
#pragma unroll
        for (int i = 0; i < 4; i++) {
            int f   = tid + i * 256;
            int row = f >> 5;                 // 0..31
            int nc  = (f & 31) * 4;           // 0..124
            uint32_t daddr = sbase + (uint32_t)((2 * ABUF + buf * BBUF + row * BPITCH + nc) * 4);
            cp_async16(daddr, B + (size_t)(k0 + row) * N + bn + nc);
        }
    };

    constexpr int NITER = GK / 32;   // 64
    issue_stage(0, 0);
    cp_commit();

    for (int it = 0; it < NITER; it++) {
        if (it + 1 < NITER) {
            issue_stage((it + 1) * 32, (it + 1) & 1);
            cp_commit();
            cp_wait<1>();
        } else {
            cp_wait<0>();
        }
        __syncthreads();

        const float* Ab = As + (it & 1) * ABUF;
        const float* Bbuf = Bs + (it & 1) * BBUF;

#pragma unroll
        for (int kc = 0; kc < 4; kc++) {
            const int k8 = kc * 8;
            uint32_t a[4][4], b[4][2];
#pragma unroll
            for (int mt = 0; mt < 4; mt++) {
                int row = mbase + mt * 16 + gid;
                a[mt][0] = __float_as_uint(Ab[row * APITCH + k8 + tig]);
                a[mt][1] = __float_as_uint(Ab[(row + 8) * APITCH + k8 + tig]);
                a[mt][2] = __float_as_uint(Ab[row * APITCH + k8 + tig + 4]);
                a[mt][3] = __float_as_uint(Ab[(row + 8) * APITCH + k8 + tig + 4]);
            }
#pragma unroll
            for (int nt = 0; nt < 4; nt++) {
                int col = nbase + nt * 8 + gid;
                b[nt][0] = __float_as_uint(Bbuf[(k8 + tig) * BPITCH + col]);
                b[nt][1] = __float_as_uint(Bbuf[(k8 + tig + 4) * BPITCH + col]);
            }
#pragma unroll
            for (int mt = 0; mt < 4; mt++)
#pragma unroll
                for (int nt = 0; nt < 4; nt++)
                    mma_tf32(d[mt][nt][0], d[mt][nt][1], d[mt][nt][2], d[mt][nt][3],
                             a[mt][0], a[mt][1], a[mt][2], a[mt][3],
                             b[nt][0], b[nt][1]);
        }
        __syncthreads();
    }

    // epilogue: d0/d1 at (row, 2*tig), d2/d3 at (row+8, 2*tig)
#pragma unroll
    for (int mt = 0; mt < 4; mt++) {
        int row = bm + mbase + mt * 16 + gid;
#pragma unroll
        for (int nt = 0; nt < 4; nt++) {
            int col = bn + nbase + nt * 8 + 2 * tig;
            *(float2*)(C + (size_t)row * N + col)       = make_float2(d[mt][nt][0], d[mt][nt][1]);
            *(float2*)(C + (size_t)(row + 8) * N + col) = make_float2(d[mt][nt][2], d[mt][nt][3]);
        }
    }
}

// ---------------------------------------------------------------------------
// RoPE + RMSNorm, one warp per (b,t,head) row of 128.
// ---------------------------------------------------------------------------
__global__ void rope_rmsnorm_kernel(const float* __restrict__ cosp,
                                    const float* __restrict__ sinp,
                                    const float* __restrict__ qk_w)
{
    const int QROWS = BT * Hh;        // 65536
    const int KROWS = BT * KVH_;      // 16384
    int warp = (blockIdx.x * blockDim.x + threadIdx.x) >> 5;
    int lane = threadIdx.x & 31;
    float* row;
    int t;
    if (warp < QROWS) {
        t = (warp / Hh) % Tt;
        row = g_q + (size_t)warp * HD_;
    } else {
        int w = warp - QROWS;
        if (w >= KROWS) return;
        t = (w / KVH_) % Tt;
        row = g_k + (size_t)w * HD_;
    }
    int j0 = lane, j1 = lane + 32;
    float x1a = row[j0],      x1b = row[j1];
    float x2a = row[j0 + 64], x2b = row[j1 + 64];
    float ca = cosp[t * 64 + j0], sa = sinp[t * 64 + j0];
    float cb = cosp[t * 64 + j1], sb = sinp[t * 64 + j1];
    float o1a = x1a * ca - x2a * sa, o2a = x2a * ca + x1a * sa;
    float o1b = x1b * cb - x2b * sb, o2b = x2b * cb + x1b * sb;
    float ss = o1a * o1a + o2a * o2a + o1b * o1b + o2b * o2b;
#pragma unroll
    for (int off = 16; off; off >>= 1) ss += __shfl_xor_sync(0xffffffffu, ss, off);
    float rms = rsqrtf(ss * (1.0f / 128.0f) + 1e-6f);
    row[j0]      = o1a * rms * qk_w[j0];
    row[j1]      = o1b * rms * qk_w[j1];
    row[j0 + 64] = o2a * rms * qk_w[j0 + 64];
    row[j1 + 64] = o2b * rms * qk_w[j1 + 64];
}

// ---------------------------------------------------------------------------
// Flash attention, fp32, causal, GQA. BM=128, BN=64, D=128, 256 threads.
// (Unchanged from passing R5 kernel, except the epilogue rounds g_y to tf32
//  so the output projection can consume it directly.)
// ---------------------------------------------------------------------------
#define QPAD 132
#define KPAD 68
#define FA_SMEM_FLOATS (128*QPAD + 128*KPAD + 64*QPAD + 64*128)

__global__ void __launch_bounds__(256, 1) flash_attn_kernel()
{
    extern __shared__ float smem[];
    float* Qst = smem;                          // [d][m] 128 x 132
    float* Kst = Qst + 128 * QPAD;              // [d][n] 128 x 68
    float* Pst = Kst + 128 * KPAD;              // [n][m] 64 x 132
    float* Vs  = Pst + 64 * QPAD;               // [n][d] 64 x 128

    const int qi = blockIdx.x, h = blockIdx.y, b = blockIdx.z;
    const int kvh = h / REP;
    const int tid = threadIdx.x;
    const int tx = tid & 15, ty = tid >> 4;
    const int r0 = ty * 4, r1 = 64 + ty * 4;
    const int cS = tx * 4;
    const int c0 = tx * 4, c1 = 64 + tx * 4;
    const float scale = 0.08838834764831845f;   // 1/sqrt(128)

    const int qbase = qi * 128;
    const float* qptr = g_q + (((size_t)b * Tt + qbase) * Hh + h) * HD_;

    for (int f = tid; f < 128 * 32; f += 256) {
        int m  = f >> 5;
        int d4 = (f & 31) * 4;
        float4 val = *(const float4*)(qptr + (size_t)m * Hh * HD_ + d4);
        Qst[(d4 + 0) * QPAD + m] = val.x * scale;
        Qst[(d4 + 1) * QPAD + m] = val.y * scale;
        Qst[(d4 + 2) * QPAD + m] = val.z * scale;
        Qst[(d4 + 3) * QPAD + m] = val.w * scale;
    }

    float o[8][8];
    float mrow[8], lrow[8];
#pragma unroll
    for (int i = 0; i < 8; i++) {
        mrow[i] = -3.0e38f; lrow[i] = 0.0f;
#pragma unroll
        for (int j = 0; j < 8; j++) o[i][j] = 0.0f;
    }

    const int ntiles = 2 * (qi + 1);
    for (int nt = 0; nt < ntiles; nt++) {
        const int kbase = nt * 64;
        __syncthreads();
        const float* kptr = g_k + (((size_t)b * Tt + kbase) * KVH_ + kvh) * HD_;
        const float* vptr = g_v + (((size_t)b * Tt + kbase) * KVH_ + kvh) * HD_;
        for (int f = tid; f < 64 * 32; f += 256) {
            int n  = f >> 5;
            int d4 = (f & 31) * 4;
            float4 kv = *(const float4*)(kptr + (size_t)n * KVH_ * HD_ + d4);
            Kst[(d4 + 0) * KPAD + n] = kv.x;
            Kst[(d4 + 1) * KPAD + n] = kv.y;
            Kst[(d4 + 2) * KPAD + n] = kv.z;
            Kst[(d4 + 3) * KPAD + n] = kv.w;
            float4 vv = *(const float4*)(vptr + (size_t)n * KVH_ * HD_ + d4);
            *(float4*)(Vs + n * 128 + d4) = vv;
        }
        __syncthreads();

        float s[8][4];
#pragma unroll
        for (int i = 0; i < 8; i++)
#pragma unroll
            for (int j = 0; j < 4; j++) s[i][j] = 0.0f;

#pragma unroll 4
        for (int kk = 0; kk < 128; kk++) {
            float4 a0 = *(float4*)(Qst + kk * QPAD + r0);
            float4 a1 = *(float4*)(Qst + kk * QPAD + r1);
            float4 bv = *(float4*)(Kst + kk * KPAD + cS);
#pragma unroll
            for (int i = 0; i < 8; i++) {
                float av = (i==0)?a0.x:(i==1)?a0.y:(i==2)?a0.z:(i==3)?a0.w:
                           (i==4)?a1.x:(i==5)?a1.y:(i==6)?a1.z:a1.w;
                s[i][0] = fmaf(av, bv.x, s[i][0]);
                s[i][1] = fmaf(av, bv.y, s[i][1]);
                s[i][2] = fmaf(av, bv.z, s[i][2]);
                s[i][3] = fmaf(av, bv.w, s[i][3]);
            }
        }

        if (kbase + 63 > qbase) {
#pragma unroll
            for (int i = 0; i < 8; i++) {
                int rg = qbase + ((i < 4) ? (r0 + i) : (r1 + i - 4));
#pragma unroll
                for (int j = 0; j < 4; j++) {
                    int cg = kbase + cS + j;
                    if (cg > rg) s[i][j] = -3.0e38f;
                }
            }
        }

#pragma unroll
        for (int i = 0; i < 8; i++) {
            float mx = fmaxf(fmaxf(s[i][0], s[i][1]), fmaxf(s[i][2], s[i][3]));
#pragma unroll
            for (int off = 8; off >= 1; off >>= 1)
                mx = fmaxf(mx, __shfl_xor_sync(0xffffffffu, mx, off, 16));
            float mnew = fmaxf(mrow[i], mx);
            float corr = __expf(mrow[i] - mnew);
            mrow[i] = mnew;
            float ls = 0.0f;
#pragma unroll
            for (int j = 0; j < 4; j++) {
                s[i][j] = __expf(s[i][j] - mnew);
                ls += s[i][j];
            }
#pragma unroll
            for (int off = 8; off >= 1; off >>= 1)
                ls += __shfl_xor_sync(0xffffffffu, ls, off, 16);
            lrow[i] = lrow[i] * corr + ls;
#pragma unroll
            for (int j = 0; j < 8; j++) o[i][j] *= corr;
        }

#pragma unroll
        for (int i = 0; i < 8; i++) {
            int rm = (i < 4) ? (r0 + i) : (r1 + i - 4);
#pragma unroll
            for (int j = 0; j < 4; j++)
                Pst[(cS + j) * QPAD + rm] = s[i][j];
        }
        __syncthreads();

#pragma unroll 4
        for (int n = 0; n < 64; n++) {
            float4 p0 = *(float4*)(Pst + n * QPAD + r0);
            float4 p1 = *(float4*)(Pst + n * QPAD + r1);
            float4 v0 = *(float4*)(Vs + n * 128 + c0);
            float4 v1 = *(float4*)(Vs + n * 128 + c1);
#pragma unroll
            for (int i = 0; i < 8; i++) {
                float pv = (i==0)?p0.x:(i==1)?p0.y:(i==2)?p0.z:(i==3)?p0.w:
                           (i==4)?p1.x:(i==5)?p1.y:(i==6)?p1.z:p1.w;
                o[i][0] = fmaf(pv, v0.x, o[i][0]);
                o[i][1] = fmaf(pv, v0.y, o[i][1]);
                o[i][2] = fmaf(pv, v0.z, o[i][2]);
                o[i][3] = fmaf(pv, v0.w, o[i][3]);
                o[i][4] = fmaf(pv, v1.x, o[i][4]);
                o[i][5] = fmaf(pv, v1.y, o[i][5]);
                o[i][6] = fmaf(pv, v1.z, o[i][6]);
                o[i][7] = fmaf(pv, v1.w, o[i][7]);
            }
        }
    }

    // epilogue: O /= l, round to tf32 (feeds output projection), store g_y
#pragma unroll
    for (int i = 0; i < 8; i++) {
        int rm = (i < 4) ? (r0 + i) : (r1 + i - 4);
        float inv = 1.0f / lrow[i];
        size_t base = (((size_t)b * Tt + qbase + rm) * Cc) + (size_t)h * HD_;
        float4 v0 = make_float4(to_tf32(o[i][0] * inv), to_tf32(o[i][1] * inv),
                                to_tf32(o[i][2] * inv), to_tf32(o[i][3] * inv));
        float4 v1 = make_float4(to_tf32(o[i][4] * inv), to_tf32(o[i][5] * inv),
                                to_tf32(o[i][6] * inv), to_tf32(o[i][7] * inv));
        *(float4*)(g_y + base + c0) = v0;
        *(float4*)(g_y + base + c1) = v1;
    }
}

// ---------------------------------------------------------------------------
// Launch
// ---------------------------------------------------------------------------
extern "C" void kernel_launch(void* const* d_in, const int* in_sizes, int n_in,
                              void* d_out, int out_size)
{
    const float* x    = (const float*)d_in[0];
    const float* cosp = (const float*)d_in[1];
    const float* sinp = (const float*)d_in[2];
    const float* wq   = (const float*)d_in[3];
    const float* wk   = (const float*)d_in[4];
    const float* wv   = (const float*)d_in[5];
    const float* wo   = (const float*)d_in[6];
    const float* qkw  = (const float*)d_in[7];
    float* out = (float*)d_out;

    // 0. round inputs to tf32 (RNE)
    {
        const int thr = 256;
        round_kernel<0><<<(BT * Cc / 4 + thr - 1) / thr, thr>>>(x,  BT * Cc / 4);
        round_kernel<1><<<(Cc * Cc / 4 + thr - 1) / thr, thr>>>(wq, Cc * Cc / 4);
        round_kernel<2><<<(Cc * KVH_ * HD_ / 4 + thr - 1) / thr, thr>>>(wk, Cc * KVH_ * HD_ / 4);
        round_kernel<3><<<(Cc * KVH_ * HD_ / 4 + thr - 1) / thr, thr>>>(wv, Cc * KVH_ * HD_ / 4);
        round_kernel<4><<<(Cc * Cc / 4 + thr - 1) / thr, thr>>>(wo, Cc * Cc / 4);
    }

    const size_t gemm_smem = GEMM_SMEM_FLOATS * sizeof(float);   // 71680 B
    cudaFuncSetAttribute(tf32_gemm<0>, cudaFuncAttributeMaxDynamicSharedMemorySize, (int)gemm_smem);
    cudaFuncSetAttribute(tf32_gemm<1>, cudaFuncAttributeMaxDynamicSharedMemorySize, (int)gemm_smem);
    cudaFuncSetAttribute(tf32_gemm<2>, cudaFuncAttributeMaxDynamicSharedMemorySize, (int)gemm_smem);
    cudaFuncSetAttribute(tf32_gemm<3>, cudaFuncAttributeMaxDynamicSharedMemorySize, (int)gemm_smem);

    // 1. QKV projections (tensor cores, tf32)
    tf32_gemm<0><<<dim3(Cc / 128, GM / 128), 256, gemm_smem>>>(nullptr);
    tf32_gemm<1><<<dim3((KVH_ * HD_) / 128, GM / 128), 256, gemm_smem>>>(nullptr);
    tf32_gemm<2><<<dim3((KVH_ * HD_) / 128, GM / 128), 256, gemm_smem>>>(nullptr);

    // 2. RoPE + RMSNorm on q and k
    {
        int total_warps = BT * Hh + BT * KVH_;   // 81920
        int threads = 256;
        int blocks = (total_warps * 32 + threads - 1) / threads;
        rope_rmsnorm_kernel<<<blocks, threads>>>(cosp, sinp, qkw);
    }

    // 3. flash attention (~169 KB dynamic smem)
    {
        size_t smem_bytes = FA_SMEM_FLOATS * sizeof(float);
        cudaFuncSetAttribute(flash_attn_kernel,
                             cudaFuncAttributeMaxDynamicSharedMemorySize,
                             (int)smem_bytes);
        flash_attn_kernel<<<dim3(Tt / 128, Hh, Bb), 256, smem_bytes>>>();
    }

    // 4. output projection (tensor cores, tf32)
    tf32_gemm<3><<<dim3(Cc / 128, GM / 128), 256, gemm_smem>>>(out);
}

// round 8
// speedup vs baseline: 3.1526x; 1.7882x over previous
#include <cuda_runtime.h>
#include <cuda_bf16.h>
#include <cstdint>

// Problem constants
#define Bb   2
#define Tt   2048
#define Cc   2048
#define Hh   16
#define KVH_ 4
#define HD_  128
#define BT   (Bb*Tt)          // 4096
#define REP  (Hh/KVH_)        // 4

// Scratch buffers (device globals: allocation-free rule).
__device__ float g_q[BT * Hh * HD_];      // (B,T,H,HD)  32MB
__device__ float g_k[BT * KVH_ * HD_];    // (B,T,KVH,HD) 8MB
__device__ float g_v[BT * KVH_ * HD_];    // 8MB
__device__ float g_y[BT * Cc];            // 32MB (tf32-rounded by FA epilogue)
// tf32-rounded copies of GEMM inputs
__device__ float g_xr[BT * Cc];           // 32MB
__device__ float g_wq_r[Cc * Cc];         // 16MB
__device__ float g_wk_r[Cc * KVH_ * HD_]; // 4MB
__device__ float g_wv_r[Cc * KVH_ * HD_]; // 4MB
__device__ float g_wo_r[Cc * Cc];         // 16MB

__device__ __forceinline__ float to_tf32(float v) {
    unsigned r;
    asm("cvt.rna.tf32.f32 %0, %1;" : "=r"(r) : "f"(v));
    return __uint_as_float(r);
}

// ---------------------------------------------------------------------------
// Pre-pass: round inputs to tf32 (RNE). R: 0=x, 1=wq, 2=wk, 3=wv, 4=wo
// ---------------------------------------------------------------------------
template<int R>
__global__ void round_kernel(const float* __restrict__ src, int n4)
{
    float* dst;
    if      (R == 0) dst = g_xr;
    else if (R == 1) dst = g_wq_r;
    else if (R == 2) dst = g_wk_r;
    else if (R == 3) dst = g_wv_r;
    else             dst = g_wo_r;
    int i = blockIdx.x * blockDim.x + threadIdx.x;
    if (i >= n4) return;
    float4 v = ((const float4*)src)[i];
    v.x = to_tf32(v.x); v.y = to_tf32(v.y);
    v.z = to_tf32(v.z); v.w = to_tf32(v.w);
    ((float4*)dst)[i] = v;
}

// ---------------------------------------------------------------------------
// tf32 mma wrapper (verified fragment layouts, R7)
// ---------------------------------------------------------------------------
__device__ __forceinline__ void mma_tf32(
    float& d0, float& d1, float& d2, float& d3,
    uint32_t a0, uint32_t a1, uint32_t a2, uint32_t a3,
    uint32_t b0, uint32_t b1)
{
    asm volatile(
        "mma.sync.aligned.m16n8k8.row.col.f32.tf32.tf32.f32 "
        "{%0,%1,%2,%3}, {%4,%5,%6,%7}, {%8,%9}, {%0,%1,%2,%3};\n"
        : "+f"(d0), "+f"(d1), "+f"(d2), "+f"(d3)
        : "r"(a0), "r"(a1), "r"(a2), "r"(a3), "r"(b0), "r"(b1));
}

__device__ __forceinline__ void cp_async16(uint32_t smem_addr, const void* gptr) {
    asm volatile("cp.async.cg.shared.global [%0], [%1], 16;\n"
                 :: "r"(smem_addr), "l"(gptr));
}
__device__ __forceinline__ void cp_commit() {
    asm volatile("cp.async.commit_group;\n");
}
template<int N>
__device__ __forceinline__ void cp_wait() {
    asm volatile("cp.async.wait_group %0;\n" :: "n"(N));
}

// ---------------------------------------------------------------------------
// tf32 tensor-core GEMM (unchanged from R7 passing kernel).
// ---------------------------------------------------------------------------
#define GK 2048
#define GM 4096
#define APITCH 36
#define BPITCH 136
#define ABUF (128 * APITCH)
#define BBUF (32 * BPITCH)
#define GEMM_SMEM_FLOATS (2 * (ABUF + BBUF))   // 71680 B

template<int OP>
__global__ void __launch_bounds__(256) tf32_gemm(float* __restrict__ Cext)
{
    constexpr int N = (OP == 1 || OP == 2) ? (KVH_ * HD_) : Cc;
    const float* A = (OP == 3) ? g_y : g_xr;
    const float* B;
    if      (OP == 0) B = g_wq_r;
    else if (OP == 1) B = g_wk_r;
    else if (OP == 2) B = g_wv_r;
    else              B = g_wo_r;
    float* C;
    if      (OP == 0) C = g_q;
    else if (OP == 1) C = g_k;
    else if (OP == 2) C = g_v;
    else              C = Cext;

    extern __shared__ float sm[];
    float* As = sm;
    float* Bs = sm + 2 * ABUF;

    const int tid  = threadIdx.x;
    const int wid  = tid >> 5;
    const int lane = tid & 31;
    const int gid  = lane >> 2;
    const int tig  = lane & 3;
    const int mbase = (wid >> 2) * 64;
    const int nbase = (wid & 3) * 32;
    const int bm = blockIdx.y * 128, bn = blockIdx.x * 128;

    float d[4][4][4];
#pragma unroll
    for (int i = 0; i < 4; i++)
#pragma unroll
        for (int j = 0; j < 4; j++)
#pragma unroll
            for (int r = 0; r < 4; r++) d[i][j][r] = 0.0f;

    uint32_t sbase = (uint32_t)__cvta_generic_to_shared(sm);

    auto issue_stage = [&](int k0, int buf) {
#pragma unroll
        for (int i = 0; i < 4; i++) {
            int f   = tid + i * 256;
            int row = f >> 3;
            int kc  = (f & 7) * 4;
            uint32_t daddr = sbase + (uint32_t)((buf * ABUF + row * APITCH + kc) * 4);
            cp_async16(daddr, A + (size_t)(bm + row) * GK + k0 + kc);
        }
#pragma unroll
        for (int i = 0; i < 4; i++) {
            int f   = tid + i * 256;
            int row = f >> 5;
            int nc  = (f & 31) * 4;
            uint32_t daddr = sbase + (uint32_t)((2 * ABUF + buf * BBUF + row * BPITCH + nc) * 4);
            cp_async16(daddr, B + (size_t)(k0 + row) * N + bn + nc);
        }
    };

    constexpr int NITER = GK / 32;
    issue_stage(0, 0);
    cp_commit();

    for (int it = 0; it < NITER; it++) {
        if (it + 1 < NITER) {
            issue_stage((it + 1) * 32, (it + 1) & 1);
            cp_commit();
            cp_wait<1>();
        } else {
            cp_wait<0>();
        }
        __syncthreads();

        const float* Ab = As + (it & 1) * ABUF;
        const float* Bbuf = Bs + (it & 1) * BBUF;

#pragma unroll
        for (int kc = 0; kc < 4; kc++) {
            const int k8 = kc * 8;
            uint32_t a[4][4], b[4][2];
#pragma unroll
            for (int mt = 0; mt < 4; mt++) {
                int row = mbase + mt * 16 + gid;
                a[mt][0] = __float_as_uint(Ab[row * APITCH + k8 + tig]);
                a[mt][1] = __float_as_uint(Ab[(row + 8) * APITCH + k8 + tig]);
                a[mt][2] = __float_as_uint(Ab[row * APITCH + k8 + tig + 4]);
                a[mt][3] = __float_as_uint(Ab[(row + 8) * APITCH + k8 + tig + 4]);
            }
#pragma unroll
            for (int nt = 0; nt < 4; nt++) {
                int col = nbase + nt * 8 + gid;
                b[nt][0] = __float_as_uint(Bbuf[(k8 + tig) * BPITCH + col]);
                b[nt][1] = __float_as_uint(Bbuf[(k8 + tig + 4) * BPITCH + col]);
            }
#pragma unroll
            for (int mt = 0; mt < 4; mt++)
#pragma unroll
                for (int nt = 0; nt < 4; nt++)
                    mma_tf32(d[mt][nt][0], d[mt][nt][1], d[mt][nt][2], d[mt][nt][3],
                             a[mt][0], a[mt][1], a[mt][2], a[mt][3],
                             b[nt][0], b[nt][1]);
        }
        __syncthreads();
    }

#pragma unroll
    for (int mt = 0; mt < 4; mt++) {
        int row = bm + mbase + mt * 16 + gid;
#pragma unroll
        for (int nt = 0; nt < 4; nt++) {
            int col = bn + nbase + nt * 8 + 2 * tig;
            *(float2*)(C + (size_t)row * N + col)       = make_float2(d[mt][nt][0], d[mt][nt][1]);
            *(float2*)(C + (size_t)(row + 8) * N + col) = make_float2(d[mt][nt][2], d[mt][nt][3]);
        }
    }
}

// ---------------------------------------------------------------------------
// RoPE + RMSNorm, one warp per (b,t,head) row of 128.
// ---------------------------------------------------------------------------
__global__ void rope_rmsnorm_kernel(const float* __restrict__ cosp,
                                    const float* __restrict__ sinp,
                                    const float* __restrict__ qk_w)
{
    const int QROWS = BT * Hh;
    const int KROWS = BT * KVH_;
    int warp = (blockIdx.x * blockDim.x + threadIdx.x) >> 5;
    int lane = threadIdx.x & 31;
    float* row;
    int t;
    if (warp < QROWS) {
        t = (warp / Hh) % Tt;
        row = g_q + (size_t)warp * HD_;
    } else {
        int w = warp - QROWS;
        if (w >= KROWS) return;
        t = (w / KVH_) % Tt;
        row = g_k + (size_t)w * HD_;
    }
    int j0 = lane, j1 = lane + 32;
    float x1a = row[j0],      x1b = row[j1];
    float x2a = row[j0 + 64], x2b = row[j1 + 64];
    float ca = cosp[t * 64 + j0], sa = sinp[t * 64 + j0];
    float cb = cosp[t * 64 + j1], sb = sinp[t * 64 + j1];
    float o1a = x1a * ca - x2a * sa, o2a = x2a * ca + x1a * sa;
    float o1b = x1b * cb - x2b * sb, o2b = x2b * cb + x1b * sb;
    float ss = o1a * o1a + o2a * o2a + o1b * o1b + o2b * o2b;
#pragma unroll
    for (int off = 16; off; off >>= 1) ss += __shfl_xor_sync(0xffffffffu, ss, off);
    float rms = rsqrtf(ss * (1.0f / 128.0f) + 1e-6f);
    row[j0]      = o1a * rms * qk_w[j0];
    row[j1]      = o1b * rms * qk_w[j1];
    row[j0 + 64] = o2a * rms * qk_w[j0 + 64];
    row[j1 + 64] = o2b * rms * qk_w[j1 + 64];
}

// ---------------------------------------------------------------------------
// Flash attention with tf32 tensor cores. BM=128, BN=64, D=128, 256 threads.
// 8 warps x 16 query rows each. S: 8 nfrag x 16 kstep mma. Softmax via quad
// shuffle. P -> warp-private smem strip (tf32) -> A operand of PV mma
// (16 nfrag x 8 kstep). O fp32 in 64 regs.
// Smem pitches: Q/K 132 (LDS bank = 4g+tig, conflict-free), V 136 (8tig+g,
// conflict-free), P 68 (4g+tig, conflict-free loads).
// ---------------------------------------------------------------------------
#define FQP 132
#define FKP 132
#define FPP 68
#define FVP 136
#define FA_SMEM_FLOATS (128*FQP + 64*FKP + 128*FPP + 64*FVP)   // 42752 fl = 171KB

__global__ void __launch_bounds__(256, 1) flash_attn_tc()
{
    extern __shared__ float smem[];
    float* Qs = smem;                   // [m=128][d] pitch FQP
    float* Ks = Qs + 128 * FQP;         // [n=64][d]  pitch FKP
    float* Ps = Ks + 64 * FKP;          // [m=128][n] pitch FPP (warp-private rows)
    float* Vs = Ps + 128 * FPP;         // [k=64][d]  pitch FVP

    const int qi = blockIdx.x, h = blockIdx.y, b = blockIdx.z;
    const int kvh = h / REP;
    const int tid = threadIdx.x;
    const int wid = tid >> 5, lane = tid & 31;
    const int g = lane >> 2, tig = lane & 3;
    const int mw = wid * 16;                  // warp row base in tile
    const int qbase = qi * 128;
    const float scale = 0.08838834764831845f; // 1/sqrt(128)

    // load Q tile: scale + round to tf32
    const float* qptr = g_q + (((size_t)b * Tt + qbase) * Hh + h) * HD_;
    for (int f = tid; f < 128 * 32; f += 256) {
        int m  = f >> 5;
        int d4 = (f & 31) * 4;
        float4 v = *(const float4*)(qptr + (size_t)m * Hh * HD_ + d4);
        v.x = to_tf32(v.x * scale); v.y = to_tf32(v.y * scale);
        v.z = to_tf32(v.z * scale); v.w = to_tf32(v.w * scale);
        *(float4*)(Qs + m * FQP + d4) = v;
    }

    float o[16][4];
    float mrow[2], lrow[2];
#pragma unroll
    for (int j = 0; j < 16; j++)
#pragma unroll
        for (int r = 0; r < 4; r++) o[j][r] = 0.0f;
    mrow[0] = mrow[1] = -3.0e38f;
    lrow[0] = lrow[1] = 0.0f;

    const int row0a = mw + g, row0b = mw + g + 8;   // local rows of this thread

    const int ntiles = 2 * (qi + 1);
    for (int nt = 0; nt < ntiles; nt++) {
        const int kbase = nt * 64;
        __syncthreads();   // Qs ready (it 0) / Vs free from prev iter
        const float* kptr = g_k + (((size_t)b * Tt + kbase) * KVH_ + kvh) * HD_;
        const float* vptr = g_v + (((size_t)b * Tt + kbase) * KVH_ + kvh) * HD_;
        for (int f = tid; f < 64 * 32; f += 256) {
            int n  = f >> 5;
            int d4 = (f & 31) * 4;
            float4 kv = *(const float4*)(kptr + (size_t)n * KVH_ * HD_ + d4);
            kv.x = to_tf32(kv.x); kv.y = to_tf32(kv.y);
            kv.z = to_tf32(kv.z); kv.w = to_tf32(kv.w);
            *(float4*)(Ks + n * FKP + d4) = kv;
            float4 vv = *(const float4*)(vptr + (size_t)n * KVH_ * HD_ + d4);
            vv.x = to_tf32(vv.x); vv.y = to_tf32(vv.y);
            vv.z = to_tf32(vv.z); vv.w = to_tf32(vv.w);
            *(float4*)(Vs + n * FVP + d4) = vv;
        }
        __syncthreads();

        // ---- S = Q @ K^T : fragments s[8][4] over 8 n-tiles ----
        float s[8][4];
#pragma unroll
        for (int j = 0; j < 8; j++)
#pragma unroll
            for (int r = 0; r < 4; r++) s[j][r] = 0.0f;

#pragma unroll
        for (int k8 = 0; k8 < 128; k8 += 8) {
            uint32_t a0 = __float_as_uint(Qs[row0a * FQP + k8 + tig]);
            uint32_t a1 = __float_as_uint(Qs[row0b * FQP + k8 + tig]);
            uint32_t a2 = __float_as_uint(Qs[row0a * FQP + k8 + tig + 4]);
            uint32_t a3 = __float_as_uint(Qs[row0b * FQP + k8 + tig + 4]);
#pragma unroll
            for (int j = 0; j < 8; j++) {
                uint32_t b0 = __float_as_uint(Ks[(j * 8 + g) * FKP + k8 + tig]);
                uint32_t b1 = __float_as_uint(Ks[(j * 8 + g) * FKP + k8 + tig + 4]);
                mma_tf32(s[j][0], s[j][1], s[j][2], s[j][3], a0, a1, a2, a3, b0, b1);
            }
        }

        // causal mask on diagonal-overlapping tiles
        if (kbase + 63 > qbase) {
            int rga = qbase + row0a, rgb = qbase + row0b;
#pragma unroll
            for (int j = 0; j < 8; j++) {
                int cg = kbase + j * 8 + 2 * tig;
                if (cg     > rga) s[j][0] = -3.0e38f;
                if (cg + 1 > rga) s[j][1] = -3.0e38f;
                if (cg     > rgb) s[j][2] = -3.0e38f;
                if (cg + 1 > rgb) s[j][3] = -3.0e38f;
            }
        }

        // ---- online softmax (rows g, g+8; row group = quad of lanes) ----
        float mx0 = -3.0e38f, mx1 = -3.0e38f;
#pragma unroll
        for (int j = 0; j < 8; j++) {
            mx0 = fmaxf(mx0, fmaxf(s[j][0], s[j][1]));
            mx1 = fmaxf(mx1, fmaxf(s[j][2], s[j][3]));
        }
        mx0 = fmaxf(mx0, __shfl_xor_sync(0xffffffffu, mx0, 1));
        mx0 = fmaxf(mx0, __shfl_xor_sync(0xffffffffu, mx0, 2));
        mx1 = fmaxf(mx1, __shfl_xor_sync(0xffffffffu, mx1, 1));
        mx1 = fmaxf(mx1, __shfl_xor_sync(0xffffffffu, mx1, 2));

        float mn0 = fmaxf(mrow[0], mx0);
        float mn1 = fmaxf(mrow[1], mx1);
        float corr0 = __expf(mrow[0] - mn0);
        float corr1 = __expf(mrow[1] - mn1);
        mrow[0] = mn0; mrow[1] = mn1;

        float ls0 = 0.0f, ls1 = 0.0f;
#pragma unroll
        for (int j = 0; j < 8; j++) {
            s[j][0] = __expf(s[j][0] - mn0);
            s[j][1] = __expf(s[j][1] - mn0);
            s[j][2] = __expf(s[j][2] - mn1);
            s[j][3] = __expf(s[j][3] - mn1);
            ls0 += s[j][0] + s[j][1];
            ls1 += s[j][2] + s[j][3];
            // store P (tf32) to warp-private strip: rows row0a/row0b
            *(float2*)(Ps + row0a * FPP + j * 8 + 2 * tig) =
                make_float2(to_tf32(s[j][0]), to_tf32(s[j][1]));
            *(float2*)(Ps + row0b * FPP + j * 8 + 2 * tig) =
                make_float2(to_tf32(s[j][2]), to_tf32(s[j][3]));
        }
        ls0 += __shfl_xor_sync(0xffffffffu, ls0, 1);
        ls0 += __shfl_xor_sync(0xffffffffu, ls0, 2);
        ls1 += __shfl_xor_sync(0xffffffffu, ls1, 1);
        ls1 += __shfl_xor_sync(0xffffffffu, ls1, 2);
        lrow[0] = lrow[0] * corr0 + ls0;
        lrow[1] = lrow[1] * corr1 + ls1;

#pragma unroll
        for (int j = 0; j < 16; j++) {
            o[j][0] *= corr0; o[j][1] *= corr0;
            o[j][2] *= corr1; o[j][3] *= corr1;
        }

        __syncwarp();   // P strip visible within warp

        // ---- O += P @ V : 16 n-tiles x 8 k-steps ----
#pragma unroll
        for (int k8 = 0; k8 < 64; k8 += 8) {
            uint32_t a0 = __float_as_uint(Ps[row0a * FPP + k8 + tig]);
            uint32_t a1 = __float_as_uint(Ps[row0b * FPP + k8 + tig]);
            uint32_t a2 = __float_as_uint(Ps[row0a * FPP + k8 + tig + 4]);
            uint32_t a3 = __float_as_uint(Ps[row0b * FPP + k8 + tig + 4]);
#pragma unroll
            for (int j = 0; j < 16; j++) {
                uint32_t b0 = __float_as_uint(Vs[(k8 + tig) * FVP + j * 8 + g]);
                uint32_t b1 = __float_as_uint(Vs[(k8 + tig + 4) * FVP + j * 8 + g]);
                mma_tf32(o[j][0], o[j][1], o[j][2], o[j][3], a0, a1, a2, a3, b0, b1);
            }
        }
    }

    // epilogue: O /= l, round to tf32 (feeds output projection), store g_y
    float inv0 = 1.0f / lrow[0], inv1 = 1.0f / lrow[1];
    size_t basea = (((size_t)b * Tt + qbase + row0a) * Cc) + (size_t)h * HD_;
    size_t baseb = (((size_t)b * Tt + qbase + row0b) * Cc) + (size_t)h * HD_;
#pragma unroll
    for (int j = 0; j < 16; j++) {
        int col = j * 8 + 2 * tig;
        *(float2*)(g_y + basea + col) =
            make_float2(to_tf32(o[j][0] * inv0), to_tf32(o[j][1] * inv0));
        *(float2*)(g_y + baseb + col) =
            make_float2(to_tf32(o[j][2] * inv1), to_tf32(o[j][3] * inv1));
    }
}

// ---------------------------------------------------------------------------
// Launch
// ---------------------------------------------------------------------------
extern "C" void kernel_launch(void* const* d_in, const int* in_sizes, int n_in,
                              void* d_out, int out_size)
{
    const float* x    = (const float*)d_in[0];
    const float* cosp = (const float*)d_in[1];
    const float* sinp = (const float*)d_in[2];
    const float* wq   = (const float*)d_in[3];
    const float* wk   = (const float*)d_in[4];
    const float* wv   = (const float*)d_in[5];
    const float* wo   = (const float*)d_in[6];
    const float* qkw  = (const float*)d_in[7];
    float* out = (float*)d_out;

    // 0. round inputs to tf32 (RNE)
    {
        const int thr = 256;
        round_kernel<0><<<(BT * Cc / 4 + thr - 1) / thr, thr>>>(x,  BT * Cc / 4);
        round_kernel<1><<<(Cc * Cc / 4 + thr - 1) / thr, thr>>>(wq, Cc * Cc / 4);
        round_kernel<2><<<(Cc * KVH_ * HD_ / 4 + thr - 1) / thr, thr>>>(wk, Cc * KVH_ * HD_ / 4);
        round_kernel<3><<<(Cc * KVH_ * HD_ / 4 + thr - 1) / thr, thr>>>(wv, Cc * KVH_ * HD_ / 4);
        round_kernel<4><<<(Cc * Cc / 4 + thr - 1) / thr, thr>>>(wo, Cc * Cc / 4);
    }

    const size_t gemm_smem = GEMM_SMEM_FLOATS * sizeof(float);
    cudaFuncSetAttribute(tf32_gemm<0>, cudaFuncAttributeMaxDynamicSharedMemorySize, (int)gemm_smem);
    cudaFuncSetAttribute(tf32_gemm<1>, cudaFuncAttributeMaxDynamicSharedMemorySize, (int)gemm_smem);
    cudaFuncSetAttribute(tf32_gemm<2>, cudaFuncAttributeMaxDynamicSharedMemorySize, (int)gemm_smem);
    cudaFuncSetAttribute(tf32_gemm<3>, cudaFuncAttributeMaxDynamicSharedMemorySize, (int)gemm_smem);

    // 1. QKV projections (tensor cores, tf32)
    tf32_gemm<0><<<dim3(Cc / 128, GM / 128), 256, gemm_smem>>>(nullptr);
    tf32_gemm<1><<<dim3((KVH_ * HD_) / 128, GM / 128), 256, gemm_smem>>>(nullptr);
    tf32_gemm<2><<<dim3((KVH_ * HD_) / 128, GM / 128), 256, gemm_smem>>>(nullptr);

    // 2. RoPE + RMSNorm on q and k
    {
        int total_warps = BT * Hh + BT * KVH_;
        int threads = 256;
        int blocks = (total_warps * 32 + threads - 1) / threads;
        rope_rmsnorm_kernel<<<blocks, threads>>>(cosp, sinp, qkw);
    }

    // 3. flash attention, tensor cores (~171 KB dynamic smem)
    {
        size_t smem_bytes = FA_SMEM_FLOATS * sizeof(float);
        cudaFuncSetAttribute(flash_attn_tc,
                             cudaFuncAttributeMaxDynamicSharedMemorySize,
                             (int)smem_bytes);
        flash_attn_tc<<<dim3(Tt / 128, Hh, Bb), 256, smem_bytes>>>();
    }

    // 4. output projection (tensor cores, tf32)
    tf32_gemm<3><<<dim3(Cc / 128, GM / 128), 256, gemm_smem>>>(out);
}

// round 9
// speedup vs baseline: 3.3551x; 1.0642x over previous
#include <cuda_runtime.h>
#include <cuda_bf16.h>
#include <cstdint>

// Problem constants
#define Bb   2
#define Tt   2048
#define Cc   2048
#define Hh   16
#define KVH_ 4
#define HD_  128
#define BT   (Bb*Tt)          // 4096
#define REP  (Hh/KVH_)        // 4

// Scratch buffers (device globals: allocation-free rule).
__device__ float g_q[BT * Hh * HD_];      // (B,T,H,HD)  32MB  (tf32 after rope)
__device__ float g_k[BT * KVH_ * HD_];    // 8MB (tf32 after rope)
__device__ float g_v[BT * KVH_ * HD_];    // 8MB (tf32 from gemm<2>)
__device__ float g_y[BT * Cc];            // 32MB (tf32 from FA epilogue)
// tf32-rounded copies of GEMM inputs
__device__ float g_xr[BT * Cc];           // 32MB
__device__ float g_wq_r[Cc * Cc];         // 16MB
__device__ float g_wk_r[Cc * KVH_ * HD_]; // 4MB
__device__ float g_wv_r[Cc * KVH_ * HD_]; // 4MB
__device__ float g_wo_r[Cc * Cc];         // 16MB

__device__ __forceinline__ float to_tf32(float v) {
    unsigned r;
    asm("cvt.rna.tf32.f32 %0, %1;" : "=r"(r) : "f"(v));
    return __uint_as_float(r);
}

// ---------------------------------------------------------------------------
// Pre-pass: round inputs to tf32 (RNE). R: 0=x, 1=wq, 2=wk, 3=wv, 4=wo
// ---------------------------------------------------------------------------
template<int R>
__global__ void round_kernel(const float* __restrict__ src, int n4)
{
    float* dst;
    if      (R == 0) dst = g_xr;
    else if (R == 1) dst = g_wq_r;
    else if (R == 2) dst = g_wk_r;
    else if (R == 3) dst = g_wv_r;
    else             dst = g_wo_r;
    int i = blockIdx.x * blockDim.x + threadIdx.x;
    if (i >= n4) return;
    float4 v = ((const float4*)src)[i];
    v.x = to_tf32(v.x); v.y = to_tf32(v.y);
    v.z = to_tf32(v.z); v.w = to_tf32(v.w);
    ((float4*)dst)[i] = v;
}

// ---------------------------------------------------------------------------
// tf32 mma wrapper (verified fragment layouts)
// ---------------------------------------------------------------------------
__device__ __forceinline__ void mma_tf32(
    float& d0, float& d1, float& d2, float& d3,
    uint32_t a0, uint32_t a1, uint32_t a2, uint32_t a3,
    uint32_t b0, uint32_t b1)
{
    asm volatile(
        "mma.sync.aligned.m16n8k8.row.col.f32.tf32.tf32.f32 "
        "{%0,%1,%2,%3}, {%4,%5,%6,%7}, {%8,%9}, {%0,%1,%2,%3};\n"
        : "+f"(d0), "+f"(d1), "+f"(d2), "+f"(d3)
        : "r"(a0), "r"(a1), "r"(a2), "r"(a3), "r"(b0), "r"(b1));
}

__device__ __forceinline__ void cp_async16(uint32_t smem_addr, const void* gptr) {
    asm volatile("cp.async.cg.shared.global [%0], [%1], 16;\n"
                 :: "r"(smem_addr), "l"(gptr));
}
__device__ __forceinline__ void cp_commit() {
    asm volatile("cp.async.commit_group;\n");
}
template<int N>
__device__ __forceinline__ void cp_wait() {
    asm volatile("cp.async.wait_group %0;\n" :: "n"(N));
}

// ---------------------------------------------------------------------------
// tf32 tensor-core GEMM (R7-verified). OP==2 rounds its output to tf32 (V).
// ---------------------------------------------------------------------------
#define GK 2048
#define GM 4096
#define APITCH 36
#define BPITCH 136
#define ABUF (128 * APITCH)
#define BBUF (32 * BPITCH)
#define GEMM_SMEM_FLOATS (2 * (ABUF + BBUF))   // 71680 B

template<int OP>
__global__ void __launch_bounds__(256) tf32_gemm(float* __restrict__ Cext)
{
    constexpr int N = (OP == 1 || OP == 2) ? (KVH_ * HD_) : Cc;
    const float* A = (OP == 3) ? g_y : g_xr;
    const float* B;
    if      (OP == 0) B = g_wq_r;
    else if (OP == 1) B = g_wk_r;
    else if (OP == 2) B = g_wv_r;
    else              B = g_wo_r;
    float* C;
    if      (OP == 0) C = g_q;
    else if (OP == 1) C = g_k;
    else if (OP == 2) C = g_v;
    else              C = Cext;

    extern __shared__ float sm[];
    float* As = sm;
    float* Bs = sm + 2 * ABUF;

    const int tid  = threadIdx.x;
    const int wid  = tid >> 5;
    const int lane = tid & 31;
    const int gid  = lane >> 2;
    const int tig  = lane & 3;
    const int mbase = (wid >> 2) * 64;
    const int nbase = (wid & 3) * 32;
    const int bm = blockIdx.y * 128, bn = blockIdx.x * 128;

    float d[4][4][4];
#pragma unroll
    for (int i = 0; i < 4; i++)
#pragma unroll
        for (int j = 0; j < 4; j++)
#pragma unroll
            for (int r = 0; r < 4; r++) d[i][j][r] = 0.0f;

    uint32_t sbase = (uint32_t)__cvta_generic_to_shared(sm);

    auto issue_stage = [&](int k0, int buf) {
#pragma unroll
        for (int i = 0; i < 4; i++) {
            int f   = tid + i * 256;
            int row = f >> 3;
            int kc  = (f & 7) * 4;
            uint32_t daddr = sbase + (uint32_t)((buf * ABUF + row * APITCH + kc) * 4);
            cp_async16(daddr, A + (size_t)(bm + row) * GK + k0 + kc);
        }
#pragma unroll
        for (int i = 0; i < 4; i++) {
            int f   = tid + i * 256;
            int row = f >> 5;
            int nc  = (f & 31) * 4;
            uint32_t daddr = sbase + (uint32_t)((2 * ABUF + buf * BBUF + row * BPITCH + nc) * 4);
            cp_async16(daddr, B + (size_t)(k0 + row) * N + bn + nc);
        }
    };

    constexpr int NITER = GK / 32;
    issue_stage(0, 0);
    cp_commit();

    for (int it = 0; it < NITER; it++) {
        if (it + 1 < NITER) {
            issue_stage((it + 1) * 32, (it + 1) & 1);
            cp_commit();
            cp_wait<1>();
        } else {
            cp_wait<0>();
        }
        __syncthreads();

        const float* Ab = As + (it & 1) * ABUF;
        const float* Bbuf = Bs + (it & 1) * BBUF;

#pragma unroll
        for (int kc = 0; kc < 4; kc++) {
            const int k8 = kc * 8;
            uint32_t a[4][4], b[4][2];
#pragma unroll
            for (int mt = 0; mt < 4; mt++) {
                int row = mbase + mt * 16 + gid;
                a[mt][0] = __float_as_uint(Ab[row * APITCH + k8 + tig]);
                a[mt][1] = __float_as_uint(Ab[(row + 8) * APITCH + k8 + tig]);
                a[mt][2] = __float_as_uint(Ab[row * APITCH + k8 + tig + 4]);
                a[mt][3] = __float_as_uint(Ab[(row + 8) * APITCH + k8 + tig + 4]);
            }
#pragma unroll
            for (int nt = 0; nt < 4; nt++) {
                int col = nbase + nt * 8 + gid;
                b[nt][0] = __float_as_uint(Bbuf[(k8 + tig) * BPITCH + col]);
                b[nt][1] = __float_as_uint(Bbuf[(k8 + tig + 4) * BPITCH + col]);
            }
#pragma unroll
            for (int mt = 0; mt < 4; mt++)
#pragma unroll
                for (int nt = 0; nt < 4; nt++)
                    mma_tf32(d[mt][nt][0], d[mt][nt][1], d[mt][nt][2], d[mt][nt][3],
                             a[mt][0], a[mt][1], a[mt][2], a[mt][3],
                             b[nt][0], b[nt][1]);
        }
        __syncthreads();
    }

#pragma unroll
    for (int mt = 0; mt < 4; mt++) {
        int row = bm + mbase + mt * 16 + gid;
#pragma unroll
        for (int nt = 0; nt < 4; nt++) {
            int col = bn + nbase + nt * 8 + 2 * tig;
            float e0 = d[mt][nt][0], e1 = d[mt][nt][1];
            float e2 = d[mt][nt][2], e3 = d[mt][nt][3];
            if (OP == 2) { e0 = to_tf32(e0); e1 = to_tf32(e1); e2 = to_tf32(e2); e3 = to_tf32(e3); }
            *(float2*)(C + (size_t)row * N + col)       = make_float2(e0, e1);
            *(float2*)(C + (size_t)(row + 8) * N + col) = make_float2(e2, e3);
        }
    }
}

// ---------------------------------------------------------------------------
// RoPE + RMSNorm, one warp per (b,t,head) row of 128. Writes tf32-rounded.
// ---------------------------------------------------------------------------
__global__ void rope_rmsnorm_kernel(const float* __restrict__ cosp,
                                    const float* __restrict__ sinp,
                                    const float* __restrict__ qk_w)
{
    const int QROWS = BT * Hh;
    const int KROWS = BT * KVH_;
    int warp = (blockIdx.x * blockDim.x + threadIdx.x) >> 5;
    int lane = threadIdx.x & 31;
    float* row;
    int t;
    if (warp < QROWS) {
        t = (warp / Hh) % Tt;
        row = g_q + (size_t)warp * HD_;
    } else {
        int w = warp - QROWS;
        if (w >= KROWS) return;
        t = (w / KVH_) % Tt;
        row = g_k + (size_t)w * HD_;
    }
    int j0 = lane, j1 = lane + 32;
    float x1a = row[j0],      x1b = row[j1];
    float x2a = row[j0 + 64], x2b = row[j1 + 64];
    float ca = cosp[t * 64 + j0], sa = sinp[t * 64 + j0];
    float cb = cosp[t * 64 + j1], sb = sinp[t * 64 + j1];
    float o1a = x1a * ca - x2a * sa, o2a = x2a * ca + x1a * sa;
    float o1b = x1b * cb - x2b * sb, o2b = x2b * cb + x1b * sb;
    float ss = o1a * o1a + o2a * o2a + o1b * o1b + o2b * o2b;
#pragma unroll
    for (int off = 16; off; off >>= 1) ss += __shfl_xor_sync(0xffffffffu, ss, off);
    float rms = rsqrtf(ss * (1.0f / 128.0f) + 1e-6f);
    row[j0]      = to_tf32(o1a * rms * qk_w[j0]);
    row[j1]      = to_tf32(o1b * rms * qk_w[j1]);
    row[j0 + 64] = to_tf32(o2a * rms * qk_w[j0 + 64]);
    row[j1 + 64] = to_tf32(o2b * rms * qk_w[j1 + 64]);
}

// ---------------------------------------------------------------------------
// Flash attention, tf32 tensor cores + cp.async pipeline.
// BM=128, BN=64, D=128, 256 threads, 8 warps x 16 rows.
// K double-buffered (prefetch at iter top), V single-buffered (issued after
// PV_i, overlaps S_{i+1}). All inputs pre-rounded to tf32 by producers.
// Scale folded into softmax. qi reversed for causal load balance.
// Smem: Qs 128x132, Ks 2x64x132, Vs 64x136, Ps 128x68  = 200 KB.
// ---------------------------------------------------------------------------
#define FQP 132
#define FKP 132
#define FPP 68
#define FVP 136
#define FA_QOFF   0
#define FA_KOFF   (128*FQP)
#define FA_VOFF   (FA_KOFF + 2*64*FKP)
#define FA_POFF   (FA_VOFF + 64*FVP)
#define FA_SMEM_FLOATS (FA_POFF + 128*FPP)   // 51200 floats = 204800 B

__global__ void __launch_bounds__(256, 1) flash_attn_tc()
{
    extern __shared__ float smem[];
    float* Qs = smem + FA_QOFF;
    float* Ks = smem + FA_KOFF;       // [2][64][FKP]
    float* Vs = smem + FA_VOFF;       // [64][FVP]
    float* Ps = smem + FA_POFF;       // [128][FPP]

    const int qi = (int)gridDim.x - 1 - (int)blockIdx.x;   // heavy blocks first
    const int h = blockIdx.y, b = blockIdx.z;
    const int kvh = h / REP;
    const int tid = threadIdx.x;
    const int wid = tid >> 5, lane = tid & 31;
    const int g = lane >> 2, tig = lane & 3;
    const int mw = wid * 16;
    const int qbase = qi * 128;
    const float scale = 0.08838834764831845f;   // 1/sqrt(128)

    uint32_t sb = (uint32_t)__cvta_generic_to_shared(smem);

    auto issue_K = [&](int t, int buf) {
        const float* kp = g_k + (((size_t)b * Tt + t * 64) * KVH_ + kvh) * HD_;
#pragma unroll
        for (int i = 0; i < 8; i++) {
            int f = tid + i * 256;
            int n = f >> 5, d4 = (f & 31) * 4;
            cp_async16(sb + (uint32_t)((FA_KOFF + buf * 64 * FKP + n * FKP + d4) * 4),
                       kp + (size_t)n * (KVH_ * HD_) + d4);
        }
    };
    auto issue_V = [&](int t) {
        const float* vp = g_v + (((size_t)b * Tt + t * 64) * KVH_ + kvh) * HD_;
#pragma unroll
        for (int i = 0; i < 8; i++) {
            int f = tid + i * 256;
            int n = f >> 5, d4 = (f & 31) * 4;
            cp_async16(sb + (uint32_t)((FA_VOFF + n * FVP + d4) * 4),
                       vp + (size_t)n * (KVH_ * HD_) + d4);
        }
    };

    // prologue: Q + K0 + V0 in group 0
    {
        const float* qptr = g_q + (((size_t)b * Tt + qbase) * Hh + h) * HD_;
#pragma unroll
        for (int i = 0; i < 16; i++) {
            int f = tid + i * 256;
            int m = f >> 5, d4 = (f & 31) * 4;
            cp_async16(sb + (uint32_t)((FA_QOFF + m * FQP + d4) * 4),
                       qptr + (size_t)m * (Hh * HD_) + d4);
        }
        issue_K(0, 0);
        issue_V(0);
        cp_commit();
    }

    float o[16][4];
    float mrow[2], lrow[2];
#pragma unroll
    for (int j = 0; j < 16; j++)
#pragma unroll
        for (int r = 0; r < 4; r++) o[j][r] = 0.0f;
    mrow[0] = mrow[1] = -3.0e38f;
    lrow[0] = lrow[1] = 0.0f;

    const int row0a = mw + g, row0b = mw + g + 8;

    const int ntiles = 2 * (qi + 1);
    for (int it = 0; it < ntiles; it++) {
        const int kbase = it * 64;

        // prefetch next K (alternate buffer)
        if (it + 1 < ntiles) issue_K(it + 1, (it + 1) & 1);
        cp_commit();
        if (it == 0) cp_wait<1>(); else cp_wait<2>();
        __syncthreads();   // K_it (+Q on it 0) visible; all warps past prior V read

        const float* Kb = Ks + (it & 1) * 64 * FKP;

        // ---- S = Q @ K^T (unscaled) ----
        float s[8][4];
#pragma unroll
        for (int j = 0; j < 8; j++)
#pragma unroll
            for (int r = 0; r < 4; r++) s[j][r] = 0.0f;

#pragma unroll
        for (int k8 = 0; k8 < 128; k8 += 8) {
            uint32_t a0 = __float_as_uint(Qs[row0a * FQP + k8 + tig]);
            uint32_t a1 = __float_as_uint(Qs[row0b * FQP + k8 + tig]);
            uint32_t a2 = __float_as_uint(Qs[row0a * FQP + k8 + tig + 4]);
            uint32_t a3 = __float_as_uint(Qs[row0b * FQP + k8 + tig + 4]);
#pragma unroll
            for (int j = 0; j < 8; j++) {
                uint32_t b0 = __float_as_uint(Kb[(j * 8 + g) * FKP + k8 + tig]);
                uint32_t b1 = __float_as_uint(Kb[(j * 8 + g) * FKP + k8 + tig + 4]);
                mma_tf32(s[j][0], s[j][1], s[j][2], s[j][3], a0, a1, a2, a3, b0, b1);
            }
        }

        // causal mask (unscaled scores)
        if (kbase + 63 > qbase) {
            int rga = qbase + row0a, rgb = qbase + row0b;
#pragma unroll
            for (int j = 0; j < 8; j++) {
                int cg = kbase + j * 8 + 2 * tig;
                if (cg     > rga) s[j][0] = -3.0e38f;
                if (cg + 1 > rga) s[j][1] = -3.0e38f;
                if (cg     > rgb) s[j][2] = -3.0e38f;
                if (cg + 1 > rgb) s[j][3] = -3.0e38f;
            }
        }

        // ---- online softmax (scale folded in) ----
        float mx0 = -3.0e38f, mx1 = -3.0e38f;
#pragma unroll
        for (int j = 0; j < 8; j++) {
            mx0 = fmaxf(mx0, fmaxf(s[j][0], s[j][1]));
            mx1 = fmaxf(mx1, fmaxf(s[j][2], s[j][3]));
        }
        mx0 = fmaxf(mx0, __shfl_xor_sync(0xffffffffu, mx0, 1));
        mx0 = fmaxf(mx0, __shfl_xor_sync(0xffffffffu, mx0, 2));
        mx1 = fmaxf(mx1, __shfl_xor_sync(0xffffffffu, mx1, 1));
        mx1 = fmaxf(mx1, __shfl_xor_sync(0xffffffffu, mx1, 2));

        float mn0 = fmaxf(mrow[0], mx0);
        float mn1 = fmaxf(mrow[1], mx1);
        float corr0 = __expf((mrow[0] - mn0) * scale);
        float corr1 = __expf((mrow[1] - mn1) * scale);
        mrow[0] = mn0; mrow[1] = mn1;
        float c0 = mn0 * scale, c1 = mn1 * scale;

        float ls0 = 0.0f, ls1 = 0.0f;
#pragma unroll
        for (int j = 0; j < 8; j++) {
            s[j][0] = __expf(fmaf(s[j][0], scale, -c0));
            s[j][1] = __expf(fmaf(s[j][1], scale, -c0));
            s[j][2] = __expf(fmaf(s[j][2], scale, -c1));
            s[j][3] = __expf(fmaf(s[j][3], scale, -c1));
            ls0 += s[j][0] + s[j][1];
            ls1 += s[j][2] + s[j][3];
            *(float2*)(Ps + row0a * FPP + j * 8 + 2 * tig) =
                make_float2(to_tf32(s[j][0]), to_tf32(s[j][1]));
            *(float2*)(Ps + row0b * FPP + j * 8 + 2 * tig) =
                make_float2(to_tf32(s[j][2]), to_tf32(s[j][3]));
        }
        ls0 += __shfl_xor_sync(0xffffffffu, ls0, 1);
        ls0 += __shfl_xor_sync(0xffffffffu, ls0, 2);
        ls1 += __shfl_xor_sync(0xffffffffu, ls1, 1);
        ls1 += __shfl_xor_sync(0xffffffffu, ls1, 2);
        lrow[0] = lrow[0] * corr0 + ls0;
        lrow[1] = lrow[1] * corr1 + ls1;

#pragma unroll
        for (int j = 0; j < 16; j++) {
            o[j][0] *= corr0; o[j][1] *= corr0;
            o[j][2] *= corr1; o[j][3] *= corr1;
        }

        // V_it must be resident before PV (allow K_{it+1} still in flight)
        cp_wait<1>();
        __syncthreads();
        __syncwarp();   // P strip ordering within warp

        // ---- O += P @ V ----
#pragma unroll
        for (int k8 = 0; k8 < 64; k8 += 8) {
            uint32_t a0 = __float_as_uint(Ps[row0a * FPP + k8 + tig]);
            uint32_t a1 = __float_as_uint(Ps[row0b * FPP + k8 + tig]);
            uint32_t a2 = __float_as_uint(Ps[row0a * FPP + k8 + tig + 4]);
            uint32_t a3 = __float_as_uint(Ps[row0b * FPP + k8 + tig + 4]);
#pragma unroll
            for (int j = 0; j < 16; j++) {
                uint32_t b0 = __float_as_uint(Vs[(k8 + tig) * FVP + j * 8 + g]);
                uint32_t b1 = __float_as_uint(Vs[(k8 + tig + 4) * FVP + j * 8 + g]);
                mma_tf32(o[j][0], o[j][1], o[j][2], o[j][3], a0, a1, a2, a3, b0, b1);
            }
        }

        // all warps done with V_it -> stream in V_{it+1} (overlaps S_{it+1})
        __syncthreads();
        if (it + 1 < ntiles) issue_V(it + 1);
        cp_commit();
    }

    // epilogue: O /= l, round to tf32 (feeds output projection), store g_y
    float inv0 = 1.0f / lrow[0], inv1 = 1.0f / lrow[1];
    size_t basea = (((size_t)b * Tt + qbase + row0a) * Cc) + (size_t)h * HD_;
    size_t baseb = (((size_t)b * Tt + qbase + row0b) * Cc) + (size_t)h * HD_;
#pragma unroll
    for (int j = 0; j < 16; j++) {
        int col = j * 8 + 2 * tig;
        *(float2*)(g_y + basea + col) =
            make_float2(to_tf32(o[j][0] * inv0), to_tf32(o[j][1] * inv0));
        *(float2*)(g_y + baseb + col) =
            make_float2(to_tf32(o[j][2] * inv1), to_tf32(o[j][3] * inv1));
    }
}

// ---------------------------------------------------------------------------
// Launch
// ---------------------------------------------------------------------------
extern "C" void kernel_launch(void* const* d_in, const int* in_sizes, int n_in,
                              void* d_out, int out_size)
{
    const float* x    = (const float*)d_in[0];
    const float* cosp = (const float*)d_in[1];
    const float* sinp = (const float*)d_in[2];
    const float* wq   = (const float*)d_in[3];
    const float* wk   = (const float*)d_in[4];
    const float* wv   = (const float*)d_in[5];
    const float* wo   = (const float*)d_in[6];
    const float* qkw  = (const float*)d_in[7];
    float* out = (float*)d_out;

    // 0. round inputs to tf32 (RNE)
    {
        const int thr = 256;
        round_kernel<0><<<(BT * Cc / 4 + thr - 1) / thr, thr>>>(x,  BT * Cc / 4);
        round_kernel<1><<<(Cc * Cc / 4 + thr - 1) / thr, thr>>>(wq, Cc * Cc / 4);
        round_kernel<2><<<(Cc * KVH_ * HD_ / 4 + thr - 1) / thr, thr>>>(wk, Cc * KVH_ * HD_ / 4);
        round_kernel<3><<<(Cc * KVH_ * HD_ / 4 + thr - 1) / thr, thr>>>(wv, Cc * KVH_ * HD_ / 4);
        round_kernel<4><<<(Cc * Cc / 4 + thr - 1) / thr, thr>>>(wo, Cc * Cc / 4);
    }

    const size_t gemm_smem = GEMM_SMEM_FLOATS * sizeof(float);
    cudaFuncSetAttribute(tf32_gemm<0>, cudaFuncAttributeMaxDynamicSharedMemorySize, (int)gemm_smem);
    cudaFuncSetAttribute(tf32_gemm<1>, cudaFuncAttributeMaxDynamicSharedMemorySize, (int)gemm_smem);
    cudaFuncSetAttribute(tf32_gemm<2>, cudaFuncAttributeMaxDynamicSharedMemorySize, (int)gemm_smem);
    cudaFuncSetAttribute(tf32_gemm<3>, cudaFuncAttributeMaxDynamicSharedMemorySize, (int)gemm_smem);

    // 1. QKV projections (tensor cores, tf32)
    tf32_gemm<0><<<dim3(Cc / 128, GM / 128), 256, gemm_smem>>>(nullptr);
    tf32_gemm<1><<<dim3((KVH_ * HD_) / 128, GM / 128), 256, gemm_smem>>>(nullptr);
    tf32_gemm<2><<<dim3((KVH_ * HD_) / 128, GM / 128), 256, gemm_smem>>>(nullptr);

    // 2. RoPE + RMSNorm on q and k (writes tf32)
    {
        int total_warps = BT * Hh + BT * KVH_;
        int threads = 256;
        int blocks = (total_warps * 32 + threads - 1) / threads;
        rope_rmsnorm_kernel<<<blocks, threads>>>(cosp, sinp, qkw);
    }

    // 3. flash attention, tensor cores + cp.async pipeline (~200 KB smem)
    {
        size_t smem_bytes = FA_SMEM_FLOATS * sizeof(float);
        cudaFuncSetAttribute(flash_attn_tc,
                             cudaFuncAttributeMaxDynamicSharedMemorySize,
                             (int)smem_bytes);
        flash_attn_tc<<<dim3(Tt / 128, Hh, Bb), 256, smem_bytes>>>();
    }

    // 4. output projection (tensor cores, tf32)
    tf32_gemm<3><<<dim3(Cc / 128, GM / 128), 256, gemm_smem>>>(out);
}

// round 10
// speedup vs baseline: 3.4034x; 1.0144x over previous
#include <cuda_runtime.h>
#include <cuda_bf16.h>
#include <cstdint>

// Problem constants
#define Bb   2
#define Tt   2048
#define Cc   2048
#define Hh   16
#define KVH_ 4
#define HD_  128
#define BT   (Bb*Tt)          // 4096
#define REP  (Hh/KVH_)        // 4

// Scratch buffers (device globals: allocation-free rule).
__device__ float g_q[BT * Hh * HD_];      // tf32 after rope
__device__ float g_k[BT * KVH_ * HD_];    // tf32 after rope
__device__ float g_v[BT * KVH_ * HD_];    // tf32 from gemm<2>
__device__ float g_y[BT * Cc];            // tf32 from FA epilogue
// tf32-rounded copies of GEMM inputs
__device__ float g_xr[BT * Cc];
__device__ float g_wq_r[Cc * Cc];
__device__ float g_wk_r[Cc * KVH_ * HD_];
__device__ float g_wv_r[Cc * KVH_ * HD_];
__device__ float g_wo_r[Cc * Cc];

__device__ __forceinline__ float to_tf32(float v) {
    unsigned r;
    asm("cvt.rna.tf32.f32 %0, %1;" : "=r"(r) : "f"(v));
    return __uint_as_float(r);
}

// ---------------------------------------------------------------------------
// Pre-pass: round inputs to tf32 (RNE). R: 0=x, 1=wq, 2=wk, 3=wv, 4=wo
// ---------------------------------------------------------------------------
template<int R>
__global__ void round_kernel(const float* __restrict__ src, int n4)
{
    float* dst;
    if      (R == 0) dst = g_xr;
    else if (R == 1) dst = g_wq_r;
    else if (R == 2) dst = g_wk_r;
    else if (R == 3) dst = g_wv_r;
    else             dst = g_wo_r;
    int i = blockIdx.x * blockDim.x + threadIdx.x;
    if (i >= n4) return;
    float4 v = ((const float4*)src)[i];
    v.x = to_tf32(v.x); v.y = to_tf32(v.y);
    v.z = to_tf32(v.z); v.w = to_tf32(v.w);
    ((float4*)dst)[i] = v;
}

// ---------------------------------------------------------------------------
// tf32 mma wrapper (verified fragment layouts)
// ---------------------------------------------------------------------------
__device__ __forceinline__ void mma_tf32(
    float& d0, float& d1, float& d2, float& d3,
    uint32_t a0, uint32_t a1, uint32_t a2, uint32_t a3,
    uint32_t b0, uint32_t b1)
{
    asm volatile(
        "mma.sync.aligned.m16n8k8.row.col.f32.tf32.tf32.f32 "
        "{%0,%1,%2,%3}, {%4,%5,%6,%7}, {%8,%9}, {%0,%1,%2,%3};\n"
        : "+f"(d0), "+f"(d1), "+f"(d2), "+f"(d3)
        : "r"(a0), "r"(a1), "r"(a2), "r"(a3), "r"(b0), "r"(b1));
}

__device__ __forceinline__ void cp_async16(uint32_t smem_addr, const void* gptr) {
    asm volatile("cp.async.cg.shared.global [%0], [%1], 16;\n"
                 :: "r"(smem_addr), "l"(gptr));
}
__device__ __forceinline__ void cp_commit() {
    asm volatile("cp.async.commit_group;\n");
}
template<int N>
__device__ __forceinline__ void cp_wait() {
    asm volatile("cp.async.wait_group %0;\n" :: "n"(N));
}

// ---------------------------------------------------------------------------
// tf32 tensor-core GEMM (R7-verified). OP==2 rounds its output to tf32 (V).
// ---------------------------------------------------------------------------
#define GK 2048
#define GM 4096
#define APITCH 36
#define BPITCH 136
#define ABUF (128 * APITCH)
#define BBUF (32 * BPITCH)
#define GEMM_SMEM_FLOATS (2 * (ABUF + BBUF))   // 71680 B

template<int OP>
__global__ void __launch_bounds__(256) tf32_gemm(float* __restrict__ Cext)
{
    constexpr int N = (OP == 1 || OP == 2) ? (KVH_ * HD_) : Cc;
    const float* A = (OP == 3) ? g_y : g_xr;
    const float* B;
    if      (OP == 0) B = g_wq_r;
    else if (OP == 1) B = g_wk_r;
    else if (OP == 2) B = g_wv_r;
    else              B = g_wo_r;
    float* C;
    if      (OP == 0) C = g_q;
    else if (OP == 1) C = g_k;
    else if (OP == 2) C = g_v;
    else              C = Cext;

    extern __shared__ float sm[];
    float* As = sm;
    float* Bs = sm + 2 * ABUF;

    const int tid  = threadIdx.x;
    const int wid  = tid >> 5;
    const int lane = tid & 31;
    const int gid  = lane >> 2;
    const int tig  = lane & 3;
    const int mbase = (wid >> 2) * 64;
    const int nbase = (wid & 3) * 32;
    const int bm = blockIdx.y * 128, bn = blockIdx.x * 128;

    float d[4][4][4];
#pragma unroll
    for (int i = 0; i < 4; i++)
#pragma unroll
        for (int j = 0; j < 4; j++)
#pragma unroll
            for (int r = 0; r < 4; r++) d[i][j][r] = 0.0f;

    uint32_t sbase = (uint32_t)__cvta_generic_to_shared(sm);

    auto issue_stage = [&](int k0, int buf) {
#pragma unroll
        for (int i = 0; i < 4; i++) {
            int f   = tid + i * 256;
            int row = f >> 3;
            int kc  = (f & 7) * 4;
            uint32_t daddr = sbase + (uint32_t)((buf * ABUF + row * APITCH + kc) * 4);
            cp_async16(daddr, A + (size_t)(bm + row) * GK + k0 + kc);
        }
#pragma unroll
        for (int i = 0; i < 4; i++) {
            int f   = tid + i * 256;
            int row = f >> 5;
            int nc  = (f & 31) * 4;
            uint32_t daddr = sbase + (uint32_t)((2 * ABUF + buf * BBUF + row * BPITCH + nc) * 4);
            cp_async16(daddr, B + (size_t)(k0 + row) * N + bn + nc);
        }
    };

    constexpr int NITER = GK / 32;
    issue_stage(0, 0);
    cp_commit();

    for (int it = 0; it < NITER; it++) {
        if (it + 1 < NITER) {
            issue_stage((it + 1) * 32, (it + 1) & 1);
            cp_commit();
            cp_wait<1>();
        } else {
            cp_wait<0>();
        }
        __syncthreads();

        const float* Ab = As + (it & 1) * ABUF;
        const float* Bbuf = Bs + (it & 1) * BBUF;

#pragma unroll
        for (int kc = 0; kc < 4; kc++) {
            const int k8 = kc * 8;
            uint32_t a[4][4], b[4][2];
#pragma unroll
            for (int mt = 0; mt < 4; mt++) {
                int row = mbase + mt * 16 + gid;
                a[mt][0] = __float_as_uint(Ab[row * APITCH + k8 + tig]);
                a[mt][1] = __float_as_uint(Ab[(row + 8) * APITCH + k8 + tig]);
                a[mt][2] = __float_as_uint(Ab[row * APITCH + k8 + tig + 4]);
                a[mt][3] = __float_as_uint(Ab[(row + 8) * APITCH + k8 + tig + 4]);
            }
#pragma unroll
            for (int nt = 0; nt < 4; nt++) {
                int col = nbase + nt * 8 + gid;
                b[nt][0] = __float_as_uint(Bbuf[(k8 + tig) * BPITCH + col]);
                b[nt][1] = __float_as_uint(Bbuf[(k8 + tig + 4) * BPITCH + col]);
            }
#pragma unroll
            for (int mt = 0; mt < 4; mt++)
#pragma unroll
                for (int nt = 0; nt < 4; nt++)
                    mma_tf32(d[mt][nt][0], d[mt][nt][1], d[mt][nt][2], d[mt][nt][3],
                             a[mt][0], a[mt][1], a[mt][2], a[mt][3],
                             b[nt][0], b[nt][1]);
        }
        __syncthreads();
    }

#pragma unroll
    for (int mt = 0; mt < 4; mt++) {
        int row = bm + mbase + mt * 16 + gid;
#pragma unroll
        for (int nt = 0; nt < 4; nt++) {
            int col = bn + nbase + nt * 8 + 2 * tig;
            float e0 = d[mt][nt][0], e1 = d[mt][nt][1];
            float e2 = d[mt][nt][2], e3 = d[mt][nt][3];
            if (OP == 2) { e0 = to_tf32(e0); e1 = to_tf32(e1); e2 = to_tf32(e2); e3 = to_tf32(e3); }
            *(float2*)(C + (size_t)row * N + col)       = make_float2(e0, e1);
            *(float2*)(C + (size_t)(row + 8) * N + col) = make_float2(e2, e3);
        }
    }
}

// ---------------------------------------------------------------------------
// RoPE + RMSNorm, one warp per (b,t,head) row of 128. Writes tf32-rounded.
// ---------------------------------------------------------------------------
__global__ void rope_rmsnorm_kernel(const float* __restrict__ cosp,
                                    const float* __restrict__ sinp,
                                    const float* __restrict__ qk_w)
{
    const int QROWS = BT * Hh;
    const int KROWS = BT * KVH_;
    int warp = (blockIdx.x * blockDim.x + threadIdx.x) >> 5;
    int lane = threadIdx.x & 31;
    float* row;
    int t;
    if (warp < QROWS) {
        t = (warp / Hh) % Tt;
        row = g_q + (size_t)warp * HD_;
    } else {
        int w = warp - QROWS;
        if (w >= KROWS) return;
        t = (w / KVH_) % Tt;
        row = g_k + (size_t)w * HD_;
    }
    int j0 = lane, j1 = lane + 32;
    float x1a = row[j0],      x1b = row[j1];
    float x2a = row[j0 + 64], x2b = row[j1 + 64];
    float ca = cosp[t * 64 + j0], sa = sinp[t * 64 + j0];
    float cb = cosp[t * 64 + j1], sb = sinp[t * 64 + j1];
    float o1a = x1a * ca - x2a * sa, o2a = x2a * ca + x1a * sa;
    float o1b = x1b * cb - x2b * sb, o2b = x2b * cb + x1b * sb;
    float ss = o1a * o1a + o2a * o2a + o1b * o1b + o2b * o2b;
#pragma unroll
    for (int off = 16; off; off >>= 1) ss += __shfl_xor_sync(0xffffffffu, ss, off);
    float rms = rsqrtf(ss * (1.0f / 128.0f) + 1e-6f);
    row[j0]      = to_tf32(o1a * rms * qk_w[j0]);
    row[j1]      = to_tf32(o1b * rms * qk_w[j1]);
    row[j0 + 64] = to_tf32(o2a * rms * qk_w[j0 + 64]);
    row[j1 + 64] = to_tf32(o2b * rms * qk_w[j1 + 64]);
}

// ---------------------------------------------------------------------------
// Flash attention, tf32 tensor cores, single-barrier pipelined iteration.
// BM=128, BN=64, D=128, 256 threads, 8 warps x 16 rows.
// Q fragments cached in registers (64 regs) after prologue; the dead Q smem
// region is reused as V buffer 1 (K and V both double-buffered).
// Per iter: wait<0> -> syncthreads -> issue K/V_{i+1} -> S -> softmax/P ->
// syncwarp -> PV.  Scale folded into softmax. qi reversed for load balance.
// Smem: Q|V1 128x132, K 2x64x132, V0 64x136, P 128x68 = 204.8 KB.
// ---------------------------------------------------------------------------
#define FQP 132
#define FKP 132
#define FPP 68
#define FVP 136
#define FA_QOFF   0
#define FA_KOFF   (128*FQP)
#define FA_VOFF   (FA_KOFF + 2*64*FKP)
#define FA_POFF   (FA_VOFF + 64*FVP)
#define FA_SMEM_FLOATS (FA_POFF + 128*FPP)   // 51200 floats = 204800 B

__global__ void __launch_bounds__(256, 1) flash_attn_tc()
{
    extern __shared__ float smem[];
    float* Qs = smem + FA_QOFF;       // staging for Q; becomes V buffer 1
    float* Ks = smem + FA_KOFF;       // [2][64][FKP]
    float* Ps = smem + FA_POFF;       // [128][FPP]

    const int qi = (int)gridDim.x - 1 - (int)blockIdx.x;   // heavy blocks first
    const int h = blockIdx.y, b = blockIdx.z;
    const int kvh = h / REP;
    const int tid = threadIdx.x;
    const int wid = tid >> 5, lane = tid & 31;
    const int g = lane >> 2, tig = lane & 3;
    const int mw = wid * 16;
    const int qbase = qi * 128;
    const float scale = 0.08838834764831845f;   // 1/sqrt(128)

    uint32_t sb = (uint32_t)__cvta_generic_to_shared(smem);

    auto issue_K = [&](int t, int buf) {
        const float* kp = g_k + (((size_t)b * Tt + t * 64) * KVH_ + kvh) * HD_;
#pragma unroll
        for (int i = 0; i < 8; i++) {
            int f = tid + i * 256;
            int n = f >> 5, d4 = (f & 31) * 4;
            cp_async16(sb + (uint32_t)((FA_KOFF + buf * 64 * FKP + n * FKP + d4) * 4),
                       kp + (size_t)n * (KVH_ * HD_) + d4);
        }
    };
    auto issue_V = [&](int t) {
        int voff = (t & 1) ? FA_QOFF : FA_VOFF;
        const float* vp = g_v + (((size_t)b * Tt + t * 64) * KVH_ + kvh) * HD_;
#pragma unroll
        for (int i = 0; i < 8; i++) {
            int f = tid + i * 256;
            int n = f >> 5, d4 = (f & 31) * 4;
            cp_async16(sb + (uint32_t)((voff + n * FVP + d4) * 4),
                       vp + (size_t)n * (KVH_ * HD_) + d4);
        }
    };

    // prologue: Q + K0 + V0 (one group)
    {
        const float* qptr = g_q + (((size_t)b * Tt + qbase) * Hh + h) * HD_;
#pragma unroll
        for (int i = 0; i < 16; i++) {
            int f = tid + i * 256;
            int m = f >> 5, d4 = (f & 31) * 4;
            cp_async16(sb + (uint32_t)((FA_QOFF + m * FQP + d4) * 4),
                       qptr + (size_t)m * (Hh * HD_) + d4);
        }
        issue_K(0, 0);
        issue_V(0);
        cp_commit();
    }

    float o[16][4];
    float mrow[2], lrow[2];
#pragma unroll
    for (int j = 0; j < 16; j++)
#pragma unroll
        for (int r = 0; r < 4; r++) o[j][r] = 0.0f;
    mrow[0] = mrow[1] = -3.0e38f;
    lrow[0] = lrow[1] = 0.0f;

    const int row0a = mw + g, row0b = mw + g + 8;
    uint32_t qa[16][4];   // Q fragments, cached for the whole KV loop

    const int ntiles = 2 * (qi + 1);
    for (int it = 0; it < ntiles; it++) {
        const int kbase = it * 64;

        cp_wait<0>();        // K_it, V_it (and Q on it 0) resident
        __syncthreads();     // all warps past previous iter's reads

        if (it == 0) {
            // cache Q fragments before V1 overwrites this region
#pragma unroll
            for (int kk = 0; kk < 16; kk++) {
                qa[kk][0] = __float_as_uint(Qs[row0a * FQP + kk * 8 + tig]);
                qa[kk][1] = __float_as_uint(Qs[row0b * FQP + kk * 8 + tig]);
                qa[kk][2] = __float_as_uint(Qs[row0a * FQP + kk * 8 + tig + 4]);
                qa[kk][3] = __float_as_uint(Qs[row0b * FQP + kk * 8 + tig + 4]);
            }
            __syncthreads();   // Q reads done before any V1 cp.async lands
        }

        if (it + 1 < ntiles) {
            issue_K(it + 1, (it + 1) & 1);
            issue_V(it + 1);
            cp_commit();
        }

        const float* Kb = Ks + (it & 1) * 64 * FKP;
        const float* Vb = smem + ((it & 1) ? FA_QOFF : FA_VOFF);

        // ---- S = Q @ K^T (unscaled) ----
        float s[8][4];
#pragma unroll
        for (int j = 0; j < 8; j++)
#pragma unroll
            for (int r = 0; r < 4; r++) s[j][r] = 0.0f;

#pragma unroll
        for (int kk = 0; kk < 16; kk++) {
            const int k8 = kk * 8;
#pragma unroll
            for (int j = 0; j < 8; j++) {
                uint32_t b0 = __float_as_uint(Kb[(j * 8 + g) * FKP + k8 + tig]);
                uint32_t b1 = __float_as_uint(Kb[(j * 8 + g) * FKP + k8 + tig + 4]);
                mma_tf32(s[j][0], s[j][1], s[j][2], s[j][3],
                         qa[kk][0], qa[kk][1], qa[kk][2], qa[kk][3], b0, b1);
            }
        }

        // causal mask (unscaled scores)
        if (kbase + 63 > qbase) {
            int rga = qbase + row0a, rgb = qbase + row0b;
#pragma unroll
            for (int j = 0; j < 8; j++) {
                int cg = kbase + j * 8 + 2 * tig;
                if (cg     > rga) s[j][0] = -3.0e38f;
                if (cg + 1 > rga) s[j][1] = -3.0e38f;
                if (cg     > rgb) s[j][2] = -3.0e38f;
                if (cg + 1 > rgb) s[j][3] = -3.0e38f;
            }
        }

        // ---- online softmax (scale folded in) ----
        float mx0 = -3.0e38f, mx1 = -3.0e38f;
#pragma unroll
        for (int j = 0; j < 8; j++) {
            mx0 = fmaxf(mx0, fmaxf(s[j][0], s[j][1]));
            mx1 = fmaxf(mx1, fmaxf(s[j][2], s[j][3]));
        }
        mx0 = fmaxf(mx0, __shfl_xor_sync(0xffffffffu, mx0, 1));
        mx0 = fmaxf(mx0, __shfl_xor_sync(0xffffffffu, mx0, 2));
        mx1 = fmaxf(mx1, __shfl_xor_sync(0xffffffffu, mx1, 1));
        mx1 = fmaxf(mx1, __shfl_xor_sync(0xffffffffu, mx1, 2));

        float mn0 = fmaxf(mrow[0], mx0);
        float mn1 = fmaxf(mrow[1], mx1);
        float corr0 = __expf((mrow[0] - mn0) * scale);
        float corr1 = __expf((mrow[1] - mn1) * scale);
        mrow[0] = mn0; mrow[1] = mn1;
        float c0 = mn0 * scale, c1 = mn1 * scale;

        float ls0 = 0.0f, ls1 = 0.0f;
#pragma unroll
        for (int j = 0; j < 8; j++) {
            s[j][0] = __expf(fmaf(s[j][0], scale, -c0));
            s[j][1] = __expf(fmaf(s[j][1], scale, -c0));
            s[j][2] = __expf(fmaf(s[j][2], scale, -c1));
            s[j][3] = __expf(fmaf(s[j][3], scale, -c1));
            ls0 += s[j][0] + s[j][1];
            ls1 += s[j][2] + s[j][3];
            *(float2*)(Ps + row0a * FPP + j * 8 + 2 * tig) =
                make_float2(to_tf32(s[j][0]), to_tf32(s[j][1]));
            *(float2*)(Ps + row0b * FPP + j * 8 + 2 * tig) =
                make_float2(to_tf32(s[j][2]), to_tf32(s[j][3]));
        }
        ls0 += __shfl_xor_sync(0xffffffffu, ls0, 1);
        ls0 += __shfl_xor_sync(0xffffffffu, ls0, 2);
        ls1 += __shfl_xor_sync(0xffffffffu, ls1, 1);
        ls1 += __shfl_xor_sync(0xffffffffu, ls1, 2);
        lrow[0] = lrow[0] * corr0 + ls0;
        lrow[1] = lrow[1] * corr1 + ls1;

#pragma unroll
        for (int j = 0; j < 16; j++) {
            o[j][0] *= corr0; o[j][1] *= corr0;
            o[j][2] *= corr1; o[j][3] *= corr1;
        }

        __syncwarp();   // P strip (warp-private rows) ordering

        // ---- O += P @ V_it ----
#pragma unroll
        for (int k8 = 0; k8 < 64; k8 += 8) {
            uint32_t a0 = __float_as_uint(Ps[row0a * FPP + k8 + tig]);
            uint32_t a1 = __float_as_uint(Ps[row0b * FPP + k8 + tig]);
            uint32_t a2 = __float_as_uint(Ps[row0a * FPP + k8 + tig + 4]);
            uint32_t a3 = __float_as_uint(Ps[row0b * FPP + k8 + tig + 4]);
#pragma unroll
            for (int j = 0; j < 16; j++) {
                uint32_t b0 = __float_as_uint(Vb[(k8 + tig) * FVP + j * 8 + g]);
                uint32_t b1 = __float_as_uint(Vb[(k8 + tig + 4) * FVP + j * 8 + g]);
                mma_tf32(o[j][0], o[j][1], o[j][2], o[j][3], a0, a1, a2, a3, b0, b1);
            }
        }
    }

    // epilogue: O /= l, round to tf32 (feeds output projection), store g_y
    float inv0 = 1.0f / lrow[0], inv1 = 1.0f / lrow[1];
    size_t basea = (((size_t)b * Tt + qbase + row0a) * Cc) + (size_t)h * HD_;
    size_t baseb = (((size_t)b * Tt + qbase + row0b) * Cc) + (size_t)h * HD_;
#pragma unroll
    for (int j = 0; j < 16; j++) {
        int col = j * 8 + 2 * tig;
        *(float2*)(g_y + basea + col) =
            make_float2(to_tf32(o[j][0] * inv0), to_tf32(o[j][1] * inv0));
        *(float2*)(g_y + baseb + col) =
            make_float2(to_tf32(o[j][2] * inv1), to_tf32(o[j][3] * inv1));
    }
}

// ---------------------------------------------------------------------------
// Launch
// ---------------------------------------------------------------------------
extern "C" void kernel_launch(void* const* d_in, const int* in_sizes, int n_in,
                              void* d_out, int out_size)
{
    const float* x    = (const float*)d_in[0];
    const float* cosp = (const float*)d_in[1];
    const float* sinp = (const float*)d_in[2];
    const float* wq   = (const float*)d_in[3];
    const float* wk   = (const float*)d_in[4];
    const float* wv   = (const float*)d_in[5];
    const float* wo   = (const float*)d_in[6];
    const float* qkw  = (const float*)d_in[7];
    float* out = (float*)d_out;

    // 0. round inputs to tf32 (RNE)
    {
        const int thr = 256;
        round_kernel<0><<<(BT * Cc / 4 + thr - 1) / thr, thr>>>(x,  BT * Cc / 4);
        round_kernel<1><<<(Cc * Cc / 4 + thr - 1) / thr, thr>>>(wq, Cc * Cc / 4);
        round_kernel<2><<<(Cc * KVH_ * HD_ / 4 + thr - 1) / thr, thr>>>(wk, Cc * KVH_ * HD_ / 4);
        round_kernel<3><<<(Cc * KVH_ * HD_ / 4 + thr - 1) / thr, thr>>>(wv, Cc * KVH_ * HD_ / 4);
        round_kernel<4><<<(Cc * Cc / 4 + thr - 1) / thr, thr>>>(wo, Cc * Cc / 4);
    }

    const size_t gemm_smem = GEMM_SMEM_FLOATS * sizeof(float);
    cudaFuncSetAttribute(tf32_gemm<0>, cudaFuncAttributeMaxDynamicSharedMemorySize, (int)gemm_smem);
    cudaFuncSetAttribute(tf32_gemm<1>, cudaFuncAttributeMaxDynamicSharedMemorySize, (int)gemm_smem);
    cudaFuncSetAttribute(tf32_gemm<2>, cudaFuncAttributeMaxDynamicSharedMemorySize, (int)gemm_smem);
    cudaFuncSetAttribute(tf32_gemm<3>, cudaFuncAttributeMaxDynamicSharedMemorySize, (int)gemm_smem);

    // 1. QKV projections (tensor cores, tf32)
    tf32_gemm<0><<<dim3(Cc / 128, GM / 128), 256, gemm_smem>>>(nullptr);
    tf32_gemm<1><<<dim3((KVH_ * HD_) / 128, GM / 128), 256, gemm_smem>>>(nullptr);
    tf32_gemm<2><<<dim3((KVH_ * HD_) / 128, GM / 128), 256, gemm_smem>>>(nullptr);

    // 2. RoPE + RMSNorm on q and k (writes tf32)
    {
        int total_warps = BT * Hh + BT * KVH_;
        int threads = 256;
        int blocks = (total_warps * 32 + threads - 1) / threads;
        rope_rmsnorm_kernel<<<blocks, threads>>>(cosp, sinp, qkw);
    }

    // 3. flash attention (single-barrier pipelined, ~200 KB smem)
    {
        size_t smem_bytes = FA_SMEM_FLOATS * sizeof(float);
        cudaFuncSetAttribute(flash_attn_tc,
                             cudaFuncAttributeMaxDynamicSharedMemorySize,
                             (int)smem_bytes);
        flash_attn_tc<<<dim3(Tt / 128, Hh, Bb), 256, smem_bytes>>>();
    }

    // 4. output projection (tensor cores, tf32)
    tf32_gemm<3><<<dim3(Cc / 128, GM / 128), 256, gemm_smem>>>(out);
}

// round 14
// speedup vs baseline: 5.3348x; 1.5675x over previous
#include <cuda_runtime.h>
#include <cuda_fp16.h>
#include <cstdint>

// Problem constants
#define Bb   2
#define Tt   2048
#define Cc   2048
#define Hh   16
#define KVH_ 4
#define HD_  128
#define BT   (Bb*Tt)          // 4096
#define REP  (Hh/KVH_)        // 4

// Scratch buffers (device globals).
__device__ float  g_q[BT * Hh * HD_];      // fp32 QKV projections (pre-rope)
__device__ float  g_k[BT * KVH_ * HD_];
__device__ __half g_xh[BT * Cc];           // fp16 x
__device__ __half g_wq_h[Cc * Cc];         // fp16 weights, TRANSPOSED [N][K]
__device__ __half g_wk_h[Cc * KVH_ * HD_];
__device__ __half g_wv_h[Cc * KVH_ * HD_];
__device__ __half g_wo_h[Cc * Cc];
__device__ __half g_qh[BT * Hh * HD_];     // fp16 q/k after rope+rmsnorm
__device__ __half g_kh[BT * KVH_ * HD_];
__device__ __half g_vt[(size_t)Bb * KVH_ * HD_ * Tt];  // fp16 V TRANSPOSED [b][kvh][d][T]
__device__ __half g_yh[BT * Cc];           // fp16 attention output

__device__ __forceinline__ uint32_t ld32h(const __half* p) {
    return *(const uint32_t*)p;
}

// ---------------------------------------------------------------------------
// Pre-pass: x fp32 -> fp16
// ---------------------------------------------------------------------------
__global__ void round_x_kernel(const float* __restrict__ src, int n4)
{
    int i = blockIdx.x * blockDim.x + threadIdx.x;
    if (i >= n4) return;
    float4 v = ((const float4*)src)[i];
    __half2* d = (__half2*)(g_xh + (size_t)i * 4);
    d[0] = __floats2half2_rn(v.x, v.y);
    d[1] = __floats2half2_rn(v.z, v.w);
}

// ---------------------------------------------------------------------------
// Pre-pass: weight [K][N] fp32 -> [N][K] fp16 (transpose).
// R: 1=wq, 2=wk, 3=wv, 4=wo.  block (32,8), grid (N/32, K/32).
// ---------------------------------------------------------------------------
template<int R>
__global__ void round_t_kernel(const float* __restrict__ src, int K, int N)
{
    __half* dst;
    if      (R == 1) dst = g_wq_h;
    else if (R == 2) dst = g_wk_h;
    else if (R == 3) dst = g_wv_h;
    else             dst = g_wo_h;
    __shared__ float tile[32][33];
    int n0 = blockIdx.x * 32, k0 = blockIdx.y * 32;
    int tx = threadIdx.x, ty = threadIdx.y;
#pragma unroll
    for (int i = 0; i < 4; i++)
        tile[ty + i * 8][tx] = src[(size_t)(k0 + ty + i * 8) * N + n0 + tx];
    __syncthreads();
#pragma unroll
    for (int i = 0; i < 4; i++)
        dst[(size_t)(n0 + ty + i * 8) * K + k0 + tx] = __float2half_rn(tile[tx][ty + i * 8]);
}

// ---------------------------------------------------------------------------
// fp16 mma m16n8k16, fp32 accumulate.
// A frag (lane g=lane>>2, t=lane&3): a0=(g, 2t..2t+1) a1=(g+8, ..)
//   a2=(g, 2t+8..9) a3=(g+8, ..). B: b0=(k 2t..2t+1, col g) b1=(k 2t+8..9, g).
// D: d0,d1=(g, 2t,2t+1) d2,d3=(g+8, ..).
// ---------------------------------------------------------------------------
__device__ __forceinline__ void mma_f16(
    float& d0, float& d1, float& d2, float& d3,
    uint32_t a0, uint32_t a1, uint32_t a2, uint32_t a3,
    uint32_t b0, uint32_t b1)
{
    asm volatile(
        "mma.sync.aligned.m16n8k16.row.col.f32.f16.f16.f32 "
        "{%0,%1,%2,%3}, {%4,%5,%6,%7}, {%8,%9}, {%0,%1,%2,%3};\n"
        : "+f"(d0), "+f"(d1), "+f"(d2), "+f"(d3)
        : "r"(a0), "r"(a1), "r"(a2), "r"(a3), "r"(b0), "r"(b1));
}

__device__ __forceinline__ void cp_async16(uint32_t smem_addr, const void* gptr) {
    asm volatile("cp.async.cg.shared.global [%0], [%1], 16;\n"
                 :: "r"(smem_addr), "l"(gptr));
}
__device__ __forceinline__ void cp_commit() {
    asm volatile("cp.async.commit_group;\n");
}
template<int N>
__device__ __forceinline__ void cp_wait() {
    asm volatile("cp.async.wait_group %0;\n" :: "n"(N));
}

// ---------------------------------------------------------------------------
// fp16 tensor-core GEMM: C[M,N] = A[M,K] @ Bt[N,K]^T.
// Tile 128x128, BK=32, 256 threads (2x4 warps, 64x32/warp), double-buffered.
// OP: 0=q->g_q(f32), 1=k->g_k(f32), 2=v->g_vt(f16 transposed), 3=out(f32).
// Smem pitch 40 halfs -> fragment LDS word-bank = 20g+tg mod 32, conflict-free.
// ---------------------------------------------------------------------------
#define GK 2048
#define GM 4096
#define HP 40    // smem pitch in halfs

template<int OP>
__global__ void __launch_bounds__(256) f16_gemm(float* __restrict__ Cext)
{
    constexpr int N = (OP == 1 || OP == 2) ? (KVH_ * HD_) : Cc;
    const __half* A = (OP == 3) ? g_yh : g_xh;
    const __half* Bt;
    if      (OP == 0) Bt = g_wq_h;
    else if (OP == 1) Bt = g_wk_h;
    else if (OP == 2) Bt = g_wv_h;
    else              Bt = g_wo_h;

    __shared__ __half As[2][128][HP];
    __shared__ __half Bs[2][128][HP];

    const int tid  = threadIdx.x;
    const int wid  = tid >> 5;
    const int lane = tid & 31;
    const int g    = lane >> 2;
    const int tg   = lane & 3;
    const int mbase = (wid >> 2) * 64;
    const int nbase = (wid & 3) * 32;
    const int bm = blockIdx.y * 128, bn = blockIdx.x * 128;

    float d[4][4][4];
#pragma unroll
    for (int i = 0; i < 4; i++)
#pragma unroll
        for (int j = 0; j < 4; j++)
#pragma unroll
            for (int r = 0; r < 4; r++) d[i][j][r] = 0.0f;

    uint32_t sbA = (uint32_t)__cvta_generic_to_shared(&As[0][0][0]);
    uint32_t sbB = (uint32_t)__cvta_generic_to_shared(&Bs[0][0][0]);

    auto issue_stage = [&](int k0, int buf) {
#pragma unroll
        for (int i = 0; i < 2; i++) {
            int f   = tid + i * 256;        // 0..511
            int row = f >> 2;
            int c   = (f & 3) * 8;          // halfs
            cp_async16(sbA + (uint32_t)((buf * 128 * HP + row * HP + c) * 2),
                       A + (size_t)(bm + row) * GK + k0 + c);
        }
#pragma unroll
        for (int i = 0; i < 2; i++) {
            int f   = tid + i * 256;
            int row = f >> 2;
            int c   = (f & 3) * 8;
            cp_async16(sbB + (uint32_t)((buf * 128 * HP + row * HP + c) * 2),
                       Bt + (size_t)(bn + row) * GK + k0 + c);
        }
        cp_commit();
    };

    constexpr int NITER = GK / 32;
    issue_stage(0, 0);

    for (int it = 0; it < NITER; it++) {
        const int bf = it & 1;
        if (it + 1 < NITER) {
            issue_stage((it + 1) * 32, (it + 1) & 1);
            cp_wait<1>();
        } else {
            cp_wait<0>();
        }
        __syncthreads();

#pragma unroll
        for (int kc = 0; kc < 2; kc++) {
            const int k16 = kc * 16;
            uint32_t a[4][4], b[4][2];
#pragma unroll
            for (int mt = 0; mt < 4; mt++) {
                int row = mbase + mt * 16 + g;
                a[mt][0] = ld32h(&As[bf][row][k16 + 2 * tg]);
                a[mt][1] = ld32h(&As[bf][row + 8][k16 + 2 * tg]);
                a[mt][2] = ld32h(&As[bf][row][k16 + 2 * tg + 8]);
                a[mt][3] = ld32h(&As[bf][row + 8][k16 + 2 * tg + 8]);
            }
#pragma unroll
            for (int nt = 0; nt < 4; nt++) {
                int col = nbase + nt * 8 + g;
                b[nt][0] = ld32h(&Bs[bf][col][k16 + 2 * tg]);
                b[nt][1] = ld32h(&Bs[bf][col][k16 + 2 * tg + 8]);
            }
#pragma unroll
            for (int mt = 0; mt < 4; mt++)
#pragma unroll
                for (int nt = 0; nt < 4; nt++)
                    mma_f16(d[mt][nt][0], d[mt][nt][1], d[mt][nt][2], d[mt][nt][3],
                            a[mt][0], a[mt][1], a[mt][2], a[mt][3],
                            b[nt][0], b[nt][1]);
        }
        __syncthreads();
    }

    // epilogue
#pragma unroll
    for (int mt = 0; mt < 4; mt++) {
        int row = bm + mbase + mt * 16 + g;
#pragma unroll
        for (int nt = 0; nt < 4; nt++) {
            int col = bn + nbase + nt * 8 + 2 * tg;
            if (OP == 0) {
                *(float2*)(g_q + (size_t)row * N + col)       = make_float2(d[mt][nt][0], d[mt][nt][1]);
                *(float2*)(g_q + (size_t)(row + 8) * N + col) = make_float2(d[mt][nt][2], d[mt][nt][3]);
            } else if (OP == 1) {
                *(float2*)(g_k + (size_t)row * N + col)       = make_float2(d[mt][nt][0], d[mt][nt][1]);
                *(float2*)(g_k + (size_t)(row + 8) * N + col) = make_float2(d[mt][nt][2], d[mt][nt][3]);
            } else if (OP == 2) {
                // V: store transposed fp16 into g_vt[b][kvh][dd][T]
#pragma unroll
                for (int rr = 0; rr < 2; rr++) {
                    int r2 = row + rr * 8;
                    int bI = r2 / Tt, t = r2 % Tt;
#pragma unroll
                    for (int cc = 0; cc < 2; cc++) {
                        int c2 = col + cc;
                        int kvh = c2 / HD_, dd = c2 % HD_;
                        g_vt[(((size_t)bI * KVH_ + kvh) * HD_ + dd) * Tt + t] =
                            __float2half_rn(d[mt][nt][rr * 2 + cc]);
                    }
                }
            } else {
                *(float2*)(Cext + (size_t)row * N + col)       = make_float2(d[mt][nt][0], d[mt][nt][1]);
                *(float2*)(Cext + (size_t)(row + 8) * N + col) = make_float2(d[mt][nt][2], d[mt][nt][3]);
            }
        }
    }
}

// ---------------------------------------------------------------------------
// RoPE + RMSNorm, one warp per row of 128. Reads fp32, writes fp16.
// ---------------------------------------------------------------------------
__global__ void rope_rmsnorm_kernel(const float* __restrict__ cosp,
                                    const float* __restrict__ sinp,
                                    const float* __restrict__ qk_w)
{
    const int QROWS = BT * Hh;
    const int KROWS = BT * KVH_;
    int warp = (blockIdx.x * blockDim.x + threadIdx.x) >> 5;
    int lane = threadIdx.x & 31;
    const float* row;
    __half* dst;
    int t;
    if (warp < QROWS) {
        t = (warp / Hh) % Tt;
        row = g_q + (size_t)warp * HD_;
        dst = g_qh + (size_t)warp * HD_;
    } else {
        int w = warp - QROWS;
        if (w >= KROWS) return;
        t = (w / KVH_) % Tt;
        row = g_k + (size_t)w * HD_;
        dst = g_kh + (size_t)w * HD_;
    }
    int j0 = lane, j1 = lane + 32;
    float x1a = row[j0],      x1b = row[j1];
    float x2a = row[j0 + 64], x2b = row[j1 + 64];
    float ca = cosp[t * 64 + j0], sa = sinp[t * 64 + j0];
    float cb = cosp[t * 64 + j1], sb = sinp[t * 64 + j1];
    float o1a = x1a * ca - x2a * sa, o2a = x2a * ca + x1a * sa;
    float o1b = x1b * cb - x2b * sb, o2b = x2b * cb + x1b * sb;
    float ss = o1a * o1a + o2a * o2a + o1b * o1b + o2b * o2b;
#pragma unroll
    for (int off = 16; off; off >>= 1) ss += __shfl_xor_sync(0xffffffffu, ss, off);
    float rms = rsqrtf(ss * (1.0f / 128.0f) + 1e-6f);
    dst[j0]      = __float2half_rn(o1a * rms * qk_w[j0]);
    dst[j1]      = __float2half_rn(o1b * rms * qk_w[j1]);
    dst[j0 + 64] = __float2half_rn(o2a * rms * qk_w[j0 + 64]);
    dst[j1 + 64] = __float2half_rn(o2b * rms * qk_w[j1 + 64]);
}

// ---------------------------------------------------------------------------
// Flash attention, fp16 m16n8k16. BM=128, BN=64, D=128, 256 threads.
// Q frags cached in regs (32); K double-buffered [n][d]; V double-buffered
// TRANSPOSED [d][n] (from g_vt); P fp16 [m][n]. Softmax fp32, scale folded.
// Pitches (halfs): Q/K 136, V/P 72 -> conflict-free b32 fragment LDS.
// Smem = 124928 B.
// ---------------------------------------------------------------------------
#define HQP 136
#define HKP 136
#define HVP 72
#define HPP 72
#define HQOFF 0
#define HKOFF (128 * HQP)                       // 17408
#define HVOFF (HKOFF + 2 * 64 * HKP)            // 34816
#define HPOFF (HVOFF + 2 * 128 * HVP)           // 53248
#define FA_SMEM_HALFS (HPOFF + 128 * HPP)       // 62464 halfs = 124928 B

__global__ void __launch_bounds__(256, 1) flash_attn_f16()
{
    extern __shared__ __half hsm[];
    __half* Ks = hsm + HKOFF;
    __half* Ps = hsm + HPOFF;

    const int qi = (int)gridDim.x - 1 - (int)blockIdx.x;   // heavy blocks first
    const int h = blockIdx.y, b = blockIdx.z;
    const int kvh = h / REP;
    const int tid = threadIdx.x;
    const int wid = tid >> 5, lane = tid & 31;
    const int g = lane >> 2, tg = lane & 3;
    const int mw = wid * 16;
    const int qbase = qi * 128;
    const float scale = 0.08838834764831845f;   // 1/sqrt(128)

    uint32_t sb = (uint32_t)__cvta_generic_to_shared(hsm);

    auto issue_K = [&](int t, int buf) {
        const __half* kp = g_kh + (((size_t)b * Tt + t * 64) * KVH_ + kvh) * HD_;
#pragma unroll
        for (int i = 0; i < 4; i++) {
            int f = tid + i * 256;           // 0..1023
            int n = f >> 4, c = (f & 15) * 8;
            cp_async16(sb + (uint32_t)((HKOFF + buf * 64 * HKP + n * HKP + c) * 2),
                       kp + (size_t)n * (KVH_ * HD_) + c);
        }
    };
    auto issue_V = [&](int t, int buf) {
        const __half* vp = g_vt + (((size_t)b * KVH_ + kvh) * HD_) * Tt + (size_t)t * 64;
#pragma unroll
        for (int i = 0; i < 4; i++) {
            int f = tid + i * 256;           // 0..1023
            int dd = f >> 3, c = (f & 7) * 8;
            cp_async16(sb + (uint32_t)((HVOFF + buf * 128 * HVP + dd * HVP + c) * 2),
                       vp + (size_t)dd * Tt + c);
        }
    };

    // prologue: Q + K0 + V0 (one group)
    {
        const __half* qptr = g_qh + (((size_t)b * Tt + qbase) * Hh + h) * HD_;
#pragma unroll
        for (int i = 0; i < 8; i++) {
            int f = tid + i * 256;           // 0..2047
            int m = f >> 4, c = (f & 15) * 8;
            cp_async16(sb + (uint32_t)((HQOFF + m * HQP + c) * 2),
                       qptr + (size_t)m * (Hh * HD_) + c);
        }
        issue_K(0, 0);
        issue_V(0, 0);
        cp_commit();
    }

    float o[16][4];
    float mrow[2], lrow[2];
#pragma unroll
    for (int j = 0; j < 16; j++)
#pragma unroll
        for (int r = 0; r < 4; r++) o[j][r] = 0.0f;
    mrow[0] = mrow[1] = -3.0e38f;
    lrow[0] = lrow[1] = 0.0f;

    const int row0a = mw + g, row0b = mw + g + 8;
    uint32_t qa[8][4];   // Q fragments: 8 k16-steps

    const int ntiles = 2 * (qi + 1);
    for (int it = 0; it < ntiles; it++) {
        const int kbase = it * 64;
        const int bf = it & 1;

        cp_wait<0>();
        __syncthreads();

        if (it == 0) {
            const __half* Qs = hsm + HQOFF;
#pragma unroll
            for (int kk = 0; kk < 8; kk++) {
                qa[kk][0] = ld32h(&Qs[row0a * HQP + kk * 16 + 2 * tg]);
                qa[kk][1] = ld32h(&Qs[row0b * HQP + kk * 16 + 2 * tg]);
                qa[kk][2] = ld32h(&Qs[row0a * HQP + kk * 16 + 2 * tg + 8]);
                qa[kk][3] = ld32h(&Qs[row0b * HQP + kk * 16 + 2 * tg + 8]);
            }
        }

        if (it + 1 < ntiles) {
            issue_K(it + 1, bf ^ 1);
            issue_V(it + 1, bf ^ 1);
            cp_commit();
        }

        const __half* Kb = Ks + bf * 64 * HKP;
        const __half* Vb = hsm + HVOFF + bf * 128 * HVP;

        // ---- S = Q @ K^T (unscaled) ----
        float s[8][4];
#pragma unroll
        for (int j = 0; j < 8; j++)
#pragma unroll
            for (int r = 0; r < 4; r++) s[j][r] = 0.0f;

#pragma unroll
        for (int kk = 0; kk < 8; kk++) {
            const int k16 = kk * 16;
#pragma unroll
            for (int j = 0; j < 8; j++) {
                uint32_t b0 = ld32h(&Kb[(j * 8 + g) * HKP + k16 + 2 * tg]);
                uint32_t b1 = ld32h(&Kb[(j * 8 + g) * HKP + k16 + 2 * tg + 8]);
                mma_f16(s[j][0], s[j][1], s[j][2], s[j][3],
                        qa[kk][0], qa[kk][1], qa[kk][2], qa[kk][3], b0, b1);
            }
        }

        // causal mask (unscaled scores)
        if (kbase + 63 > qbase) {
            int rga = qbase + row0a, rgb = qbase + row0b;
#pragma unroll
            for (int j = 0; j < 8; j++) {
                int cg = kbase + j * 8 + 2 * tg;
                if (cg     > rga) s[j][0] = -3.0e38f;
                if (cg + 1 > rga) s[j][1] = -3.0e38f;
                if (cg     > rgb) s[j][2] = -3.0e38f;
                if (cg + 1 > rgb) s[j][3] = -3.0e38f;
            }
        }

        // ---- online softmax (fp32, scale folded) ----
        float mx0 = -3.0e38f, mx1 = -3.0e38f;
#pragma unroll
        for (int j = 0; j < 8; j++) {
            mx0 = fmaxf(mx0, fmaxf(s[j][0], s[j][1]));
            mx1 = fmaxf(mx1, fmaxf(s[j][2], s[j][3]));
        }
        mx0 = fmaxf(mx0, __shfl_xor_sync(0xffffffffu, mx0, 1));
        mx0 = fmaxf(mx0, __shfl_xor_sync(0xffffffffu, mx0, 2));
        mx1 = fmaxf(mx1, __shfl_xor_sync(0xffffffffu, mx1, 1));
        mx1 = fmaxf(mx1, __shfl_xor_sync(0xffffffffu, mx1, 2));

        float mn0 = fmaxf(mrow[0], mx0);
        float mn1 = fmaxf(mrow[1], mx1);
        float corr0 = __expf((mrow[0] - mn0) * scale);
        float corr1 = __expf((mrow[1] - mn1) * scale);
        mrow[0] = mn0; mrow[1] = mn1;
        float c0 = mn0 * scale, c1 = mn1 * scale;

        float ls0 = 0.0f, ls1 = 0.0f;
#pragma unroll
        for (int j = 0; j < 8; j++) {
            s[j][0] = __expf(fmaf(s[j][0], scale, -c0));
            s[j][1] = __expf(fmaf(s[j][1], scale, -c0));
            s[j][2] = __expf(fmaf(s[j][2], scale, -c1));
            s[j][3] = __expf(fmaf(s[j][3], scale, -c1));
            ls0 += s[j][0] + s[j][1];
            ls1 += s[j][2] + s[j][3];
            *(__half2*)(Ps + row0a * HPP + j * 8 + 2 * tg) = __floats2half2_rn(s[j][0], s[j][1]);
            *(__half2*)(Ps + row0b * HPP + j * 8 + 2 * tg) = __floats2half2_rn(s[j][2], s[j][3]);
        }
        ls0 += __shfl_xor_sync(0xffffffffu, ls0, 1);
        ls0 += __shfl_xor_sync(0xffffffffu, ls0, 2);
        ls1 += __shfl_xor_sync(0xffffffffu, ls1, 1);
        ls1 += __shfl_xor_sync(0xffffffffu, ls1, 2);
        lrow[0] = lrow[0] * corr0 + ls0;
        lrow[1] = lrow[1] * corr1 + ls1;

#pragma unroll
        for (int j = 0; j < 16; j++) {
            o[j][0] *= corr0; o[j][1] *= corr0;
            o[j][2] *= corr1; o[j][3] *= corr1;
        }

        __syncwarp();   // P strip (warp-private rows)

        // ---- O += P @ V (V transposed [d][n] in smem) ----
#pragma unroll
        for (int k16 = 0; k16 < 64; k16 += 16) {
            uint32_t a0 = ld32h(&Ps[row0a * HPP + k16 + 2 * tg]);
            uint32_t a1 = ld32h(&Ps[row0b * HPP + k16 + 2 * tg]);
            uint32_t a2 = ld32h(&Ps[row0a * HPP + k16 + 2 * tg + 8]);
            uint32_t a3 = ld32h(&Ps[row0b * HPP + k16 + 2 * tg + 8]);
#pragma unroll
            for (int j = 0; j < 16; j++) {
                uint32_t b0 = ld32h(&Vb[(j * 8 + g) * HVP + k16 + 2 * tg]);
                uint32_t b1 = ld32h(&Vb[(j * 8 + g) * HVP + k16 + 2 * tg + 8]);
                mma_f16(o[j][0], o[j][1], o[j][2], o[j][3], a0, a1, a2, a3, b0, b1);
            }
        }
    }

    // epilogue: O /= l, write fp16 to g_yh (B,T,C) at column h*HD + d
    float inv0 = 1.0f / lrow[0], inv1 = 1.0f / lrow[1];
    size_t basea = (((size_t)b * Tt + qbase + row0a) * Cc) + (size_t)h * HD_;
    size_t baseb = (((size_t)b * Tt + qbase + row0b) * Cc) + (size_t)h * HD_;
#pragma unroll
    for (int j = 0; j < 16; j++) {
        int col = j * 8 + 2 * tg;
        *(__half2*)(g_yh + basea + col) = __floats2half2_rn(o[j][0] * inv0, o[j][1] * inv0);
        *(__half2*)(g_yh + baseb + col) = __floats2half2_rn(o[j][2] * inv1, o[j][3] * inv1);
    }
}

// ---------------------------------------------------------------------------
// Launch
// ---------------------------------------------------------------------------
extern "C" void kernel_launch(void* const* d_in, const int* in_sizes, int n_in,
                              void* d_out, int out_size)
{
    const float* x    = (const float*)d_in[0];
    const float* cosp = (const float*)d_in[1];
    const float* sinp = (const float*)d_in[2];
    const float* wq   = (const float*)d_in[3];
    const float* wk   = (const float*)d_in[4];
    const float* wv   = (const float*)d_in[5];
    const float* wo   = (const float*)d_in[6];
    const float* qkw  = (const float*)d_in[7];
    float* out = (float*)d_out;

    // 0. convert x -> fp16; weights -> transposed fp16
    {
        const int thr = 256;
        round_x_kernel<<<(BT * Cc / 4 + thr - 1) / thr, thr>>>(x, BT * Cc / 4);
        dim3 tb(32, 8);
        round_t_kernel<1><<<dim3(Cc / 32, Cc / 32), tb>>>(wq, Cc, Cc);
        round_t_kernel<2><<<dim3((KVH_ * HD_) / 32, Cc / 32), tb>>>(wk, Cc, KVH_ * HD_);
        round_t_kernel<3><<<dim3((KVH_ * HD_) / 32, Cc / 32), tb>>>(wv, Cc, KVH_ * HD_);
        round_t_kernel<4><<<dim3(Cc / 32, Cc / 32), tb>>>(wo, Cc, Cc);
    }

    // 1. QKV projections (fp16 tensor cores)
    f16_gemm<0><<<dim3(Cc / 128, GM / 128), 256>>>(nullptr);
    f16_gemm<1><<<dim3((KVH_ * HD_) / 128, GM / 128), 256>>>(nullptr);
    f16_gemm<2><<<dim3((KVH_ * HD_) / 128, GM / 128), 256>>>(nullptr);

    // 2. RoPE + RMSNorm (fp32 in, fp16 out)
    {
        int total_warps = BT * Hh + BT * KVH_;
        int threads = 256;
        int blocks = (total_warps * 32 + threads - 1) / threads;
        rope_rmsnorm_kernel<<<blocks, threads>>>(cosp, sinp, qkw);
    }

    // 3. flash attention (fp16 m16n8k16, ~125 KB smem)
    {
        size_t smem_bytes = FA_SMEM_HALFS * sizeof(__half);
        cudaFuncSetAttribute(flash_attn_f16,
                             cudaFuncAttributeMaxDynamicSharedMemorySize,
                             (int)smem_bytes);
        flash_attn_f16<<<dim3(Tt / 128, Hh, Bb), 256, smem_bytes>>>();
    }

    // 4. output projection (fp16 tensor cores, fp32 out)
    f16_gemm<3><<<dim3(Cc / 128, GM / 128), 256>>>(out);
}

// round 15
// speedup vs baseline: 5.7189x; 1.0720x over previous
#include <cuda_runtime.h>
#include <cuda_fp16.h>
#include <cstdint>

// Problem constants
#define Bb   2
#define Tt   2048
#define Cc   2048
#define Hh   16
#define KVH_ 4
#define HD_  128
#define BT   (Bb*Tt)          // 4096
#define REP  (Hh/KVH_)        // 4

// Scratch buffers (device globals).
__device__ float  g_q[BT * Hh * HD_];      // fp32 QKV projections (pre-rope)
__device__ float  g_k[BT * KVH_ * HD_];
__device__ __half g_xh[BT * Cc];           // fp16 x
__device__ __half g_wq_h[Cc * Cc];         // fp16 weights, TRANSPOSED [N][K]
__device__ __half g_wk_h[Cc * KVH_ * HD_];
__device__ __half g_wv_h[Cc * KVH_ * HD_];
__device__ __half g_wo_h[Cc * Cc];
__device__ __half g_qh[BT * Hh * HD_];     // fp16 q/k after rope+rmsnorm
__device__ __half g_kh[BT * KVH_ * HD_];
__device__ __half g_vt[(size_t)Bb * KVH_ * HD_ * Tt];  // fp16 V TRANSPOSED [b][kvh][d][T]
__device__ __half g_yh[BT * Cc];           // fp16 attention output

// ---------------------------------------------------------------------------
// ldmatrix x4: four 8x8 b16 tiles -> 4 b32 fragment regs.
// ---------------------------------------------------------------------------
__device__ __forceinline__ void ldsm_x4(uint32_t& r0, uint32_t& r1,
                                        uint32_t& r2, uint32_t& r3,
                                        uint32_t saddr)
{
    asm volatile("ldmatrix.sync.aligned.m8n8.x4.shared.b16 {%0,%1,%2,%3}, [%4];"
                 : "=r"(r0), "=r"(r1), "=r"(r2), "=r"(r3) : "r"(saddr));
}

// ---------------------------------------------------------------------------
// Pre-pass: x fp32 -> fp16
// ---------------------------------------------------------------------------
__global__ void round_x_kernel(const float* __restrict__ src, int n4)
{
    int i = blockIdx.x * blockDim.x + threadIdx.x;
    if (i >= n4) return;
    float4 v = ((const float4*)src)[i];
    __half2* d = (__half2*)(g_xh + (size_t)i * 4);
    d[0] = __floats2half2_rn(v.x, v.y);
    d[1] = __floats2half2_rn(v.z, v.w);
}

// ---------------------------------------------------------------------------
// Pre-pass: weight [K][N] fp32 -> [N][K] fp16 (transpose).
// ---------------------------------------------------------------------------
template<int R>
__global__ void round_t_kernel(const float* __restrict__ src, int K, int N)
{
    __half* dst;
    if      (R == 1) dst = g_wq_h;
    else if (R == 2) dst = g_wk_h;
    else if (R == 3) dst = g_wv_h;
    else             dst = g_wo_h;
    __shared__ float tile[32][33];
    int n0 = blockIdx.x * 32, k0 = blockIdx.y * 32;
    int tx = threadIdx.x, ty = threadIdx.y;
#pragma unroll
    for (int i = 0; i < 4; i++)
        tile[ty + i * 8][tx] = src[(size_t)(k0 + ty + i * 8) * N + n0 + tx];
    __syncthreads();
#pragma unroll
    for (int i = 0; i < 4; i++)
        dst[(size_t)(n0 + ty + i * 8) * K + k0 + tx] = __float2half_rn(tile[tx][ty + i * 8]);
}

// ---------------------------------------------------------------------------
// fp16 mma m16n8k16, fp32 accumulate (R14-verified layouts).
// ---------------------------------------------------------------------------
__device__ __forceinline__ void mma_f16(
    float& d0, float& d1, float& d2, float& d3,
    uint32_t a0, uint32_t a1, uint32_t a2, uint32_t a3,
    uint32_t b0, uint32_t b1)
{
    asm volatile(
        "mma.sync.aligned.m16n8k16.row.col.f32.f16.f16.f32 "
        "{%0,%1,%2,%3}, {%4,%5,%6,%7}, {%8,%9}, {%0,%1,%2,%3};\n"
        : "+f"(d0), "+f"(d1), "+f"(d2), "+f"(d3)
        : "r"(a0), "r"(a1), "r"(a2), "r"(a3), "r"(b0), "r"(b1));
}

__device__ __forceinline__ void cp_async16(uint32_t smem_addr, const void* gptr) {
    asm volatile("cp.async.cg.shared.global [%0], [%1], 16;\n"
                 :: "r"(smem_addr), "l"(gptr));
}
__device__ __forceinline__ void cp_commit() {
    asm volatile("cp.async.commit_group;\n");
}
template<int N>
__device__ __forceinline__ void cp_wait() {
    asm volatile("cp.async.wait_group %0;\n" :: "n"(N));
}

// ---------------------------------------------------------------------------
// fp16 tensor-core GEMM with LDSM fragment loads.
// Tile 128x128, BK=32, 256 threads (2x4 warps, 64x32/warp), double-buffered.
// OP: 0=q->g_q(f32), 1=k->g_k(f32), 2=v->g_vt(f16 transposed), 3=out(f32).
// ---------------------------------------------------------------------------
#define GK 2048
#define GM 4096
#define HP 40    // smem pitch in halfs (80B rows; LDSM rows hit banks 20r mod 32)

template<int OP>
__global__ void __launch_bounds__(256) f16_gemm(float* __restrict__ Cext)
{
    constexpr int N = (OP == 1 || OP == 2) ? (KVH_ * HD_) : Cc;
    const __half* A = (OP == 3) ? g_yh : g_xh;
    const __half* Bt;
    if      (OP == 0) Bt = g_wq_h;
    else if (OP == 1) Bt = g_wk_h;
    else if (OP == 2) Bt = g_wv_h;
    else              Bt = g_wo_h;

    __shared__ __half As[2][128][HP];
    __shared__ __half Bs[2][128][HP];

    const int tid  = threadIdx.x;
    const int wid  = tid >> 5;
    const int lane = tid & 31;
    const int g    = lane >> 2;
    const int tg   = lane & 3;
    const int mbase = (wid >> 2) * 64;
    const int nbase = (wid & 3) * 32;
    const int bm = blockIdx.y * 128, bn = blockIdx.x * 128;

    // LDSM lane-address offsets:
    // A-pattern: matrices (row+0 lo, row+8 lo, row+0 hi, row+8 hi)
    const int lrowA = (lane & 7) + ((lane >> 3) & 1) * 8;   // row offset within 16
    const int lcolA = (lane >> 4) * 8;                      // k offset 0/8
    // B-pattern: matrices (blk j lo, j hi, j+1 lo, j+1 hi)
    const int lrowB = ((lane >> 4) & 1) * 8 + (lane & 7);   // row offset within 16 (j..j+1)
    const int lcolB = ((lane >> 3) & 1) * 8;                // k offset 0/8

    float d[4][4][4];
#pragma unroll
    for (int i = 0; i < 4; i++)
#pragma unroll
        for (int j = 0; j < 4; j++)
#pragma unroll
            for (int r = 0; r < 4; r++) d[i][j][r] = 0.0f;

    uint32_t sbA = (uint32_t)__cvta_generic_to_shared(&As[0][0][0]);
    uint32_t sbB = (uint32_t)__cvta_generic_to_shared(&Bs[0][0][0]);

    auto issue_stage = [&](int k0, int buf) {
#pragma unroll
        for (int i = 0; i < 2; i++) {
            int f   = tid + i * 256;        // 0..511
            int row = f >> 2;
            int c   = (f & 3) * 8;          // halfs
            cp_async16(sbA + (uint32_t)((buf * 128 * HP + row * HP + c) * 2),
                       A + (size_t)(bm + row) * GK + k0 + c);
        }
#pragma unroll
        for (int i = 0; i < 2; i++) {
            int f   = tid + i * 256;
            int row = f >> 2;
            int c   = (f & 3) * 8;
            cp_async16(sbB + (uint32_t)((buf * 128 * HP + row * HP + c) * 2),
                       Bt + (size_t)(bn + row) * GK + k0 + c);
        }
        cp_commit();
    };

    constexpr int NITER = GK / 32;
    issue_stage(0, 0);

    for (int it = 0; it < NITER; it++) {
        const int bf = it & 1;
        if (it + 1 < NITER) {
            issue_stage((it + 1) * 32, (it + 1) & 1);
            cp_wait<1>();
        } else {
            cp_wait<0>();
        }
        __syncthreads();

#pragma unroll
        for (int kc = 0; kc < 2; kc++) {
            const int k16 = kc * 16;
            uint32_t a[4][4], b[4][2];
#pragma unroll
            for (int mt = 0; mt < 4; mt++) {
                uint32_t addr = (uint32_t)__cvta_generic_to_shared(
                    &As[bf][mbase + mt * 16 + lrowA][k16 + lcolA]);
                ldsm_x4(a[mt][0], a[mt][1], a[mt][2], a[mt][3], addr);
            }
#pragma unroll
            for (int nt = 0; nt < 4; nt += 2) {
                uint32_t addr = (uint32_t)__cvta_generic_to_shared(
                    &Bs[bf][nbase + nt * 8 + lrowB][k16 + lcolB]);
                ldsm_x4(b[nt][0], b[nt][1], b[nt + 1][0], b[nt + 1][1], addr);
            }
#pragma unroll
            for (int mt = 0; mt < 4; mt++)
#pragma unroll
                for (int nt = 0; nt < 4; nt++)
                    mma_f16(d[mt][nt][0], d[mt][nt][1], d[mt][nt][2], d[mt][nt][3],
                            a[mt][0], a[mt][1], a[mt][2], a[mt][3],
                            b[nt][0], b[nt][1]);
        }
        __syncthreads();
    }

    // epilogue
#pragma unroll
    for (int mt = 0; mt < 4; mt++) {
        int row = bm + mbase + mt * 16 + g;
#pragma unroll
        for (int nt = 0; nt < 4; nt++) {
            int col = bn + nbase + nt * 8 + 2 * tg;
            if (OP == 0) {
                *(float2*)(g_q + (size_t)row * N + col)       = make_float2(d[mt][nt][0], d[mt][nt][1]);
                *(float2*)(g_q + (size_t)(row + 8) * N + col) = make_float2(d[mt][nt][2], d[mt][nt][3]);
            } else if (OP == 1) {
                *(float2*)(g_k + (size_t)row * N + col)       = make_float2(d[mt][nt][0], d[mt][nt][1]);
                *(float2*)(g_k + (size_t)(row + 8) * N + col) = make_float2(d[mt][nt][2], d[mt][nt][3]);
            } else if (OP == 2) {
                // V: store transposed fp16 into g_vt[b][kvh][dd][T]
#pragma unroll
                for (int rr = 0; rr < 2; rr++) {
                    int r2 = row + rr * 8;
                    int bI = r2 / Tt, t = r2 % Tt;
#pragma unroll
                    for (int cc = 0; cc < 2; cc++) {
                        int c2 = col + cc;
                        int kvh = c2 / HD_, dd = c2 % HD_;
                        g_vt[(((size_t)bI * KVH_ + kvh) * HD_ + dd) * Tt + t] =
                            __float2half_rn(d[mt][nt][rr * 2 + cc]);
                    }
                }
            } else {
                *(float2*)(Cext + (size_t)row * N + col)       = make_float2(d[mt][nt][0], d[mt][nt][1]);
                *(float2*)(Cext + (size_t)(row + 8) * N + col) = make_float2(d[mt][nt][2], d[mt][nt][3]);
            }
        }
    }
}

// ---------------------------------------------------------------------------
// RoPE + RMSNorm, one warp per row of 128. Reads fp32, writes fp16.
// ---------------------------------------------------------------------------
__global__ void rope_rmsnorm_kernel(const float* __restrict__ cosp,
                                    const float* __restrict__ sinp,
                                    const float* __restrict__ qk_w)
{
    const int QROWS = BT * Hh;
    const int KROWS = BT * KVH_;
    int warp = (blockIdx.x * blockDim.x + threadIdx.x) >> 5;
    int lane = threadIdx.x & 31;
    const float* row;
    __half* dst;
    int t;
    if (warp < QROWS) {
        t = (warp / Hh) % Tt;
        row = g_q + (size_t)warp * HD_;
        dst = g_qh + (size_t)warp * HD_;
    } else {
        int w = warp - QROWS;
        if (w >= KROWS) return;
        t = (w / KVH_) % Tt;
        row = g_k + (size_t)w * HD_;
        dst = g_kh + (size_t)w * HD_;
    }
    int j0 = lane, j1 = lane + 32;
    float x1a = row[j0],      x1b = row[j1];
    float x2a = row[j0 + 64], x2b = row[j1 + 64];
    float ca = cosp[t * 64 + j0], sa = sinp[t * 64 + j0];
    float cb = cosp[t * 64 + j1], sb = sinp[t * 64 + j1];
    float o1a = x1a * ca - x2a * sa, o2a = x2a * ca + x1a * sa;
    float o1b = x1b * cb - x2b * sb, o2b = x2b * cb + x1b * sb;
    float ss = o1a * o1a + o2a * o2a + o1b * o1b + o2b * o2b;
#pragma unroll
    for (int off = 16; off; off >>= 1) ss += __shfl_xor_sync(0xffffffffu, ss, off);
    float rms = rsqrtf(ss * (1.0f / 128.0f) + 1e-6f);
    dst[j0]      = __float2half_rn(o1a * rms * qk_w[j0]);
    dst[j1]      = __float2half_rn(o1b * rms * qk_w[j1]);
    dst[j0 + 64] = __float2half_rn(o2a * rms * qk_w[j0 + 64]);
    dst[j1 + 64] = __float2half_rn(o2b * rms * qk_w[j1 + 64]);
}

// ---------------------------------------------------------------------------
// Flash attention, fp16 m16n8k16 + LDSM fragment loads.
// BM=128, BN=64, D=128, 256 threads, 8 warps x 16 rows.
// Q frags cached in regs; K double-buffered [n][d]; V double-buffered
// TRANSPOSED [d][n]; P fp16 [m][n]. Softmax fp32, scale folded.
// Pitches (halfs): Q/K 136, V/P 72. Smem = 124928 B.
// ---------------------------------------------------------------------------
#define HQP 136
#define HKP 136
#define HVP 72
#define HPP 72
#define HQOFF 0
#define HKOFF (128 * HQP)                       // 17408
#define HVOFF (HKOFF + 2 * 64 * HKP)            // 34816
#define HPOFF (HVOFF + 2 * 128 * HVP)           // 53248
#define FA_SMEM_HALFS (HPOFF + 128 * HPP)       // 62464 halfs = 124928 B

__global__ void __launch_bounds__(256, 1) flash_attn_f16()
{
    extern __shared__ __half hsm[];

    const int qi = (int)gridDim.x - 1 - (int)blockIdx.x;   // heavy blocks first
    const int h = blockIdx.y, b = blockIdx.z;
    const int kvh = h / REP;
    const int tid = threadIdx.x;
    const int wid = tid >> 5, lane = tid & 31;
    const int g = lane >> 2, tg = lane & 3;
    const int mw = wid * 16;
    const int qbase = qi * 128;
    const float scale = 0.08838834764831845f;   // 1/sqrt(128)

    uint32_t sb = (uint32_t)__cvta_generic_to_shared(hsm);

    // LDSM lane-address offsets (same mapping as GEMM)
    const int lrowA = (lane & 7) + ((lane >> 3) & 1) * 8;
    const int lcolA = (lane >> 4) * 8;
    const int lrowB = ((lane >> 4) & 1) * 8 + (lane & 7);
    const int lcolB = ((lane >> 3) & 1) * 8;

    auto issue_K = [&](int t, int buf) {
        const __half* kp = g_kh + (((size_t)b * Tt + t * 64) * KVH_ + kvh) * HD_;
#pragma unroll
        for (int i = 0; i < 4; i++) {
            int f = tid + i * 256;           // 0..1023
            int n = f >> 4, c = (f & 15) * 8;
            cp_async16(sb + (uint32_t)((HKOFF + buf * 64 * HKP + n * HKP + c) * 2),
                       kp + (size_t)n * (KVH_ * HD_) + c);
        }
    };
    auto issue_V = [&](int t, int buf) {
        const __half* vp = g_vt + (((size_t)b * KVH_ + kvh) * HD_) * Tt + (size_t)t * 64;
#pragma unroll
        for (int i = 0; i < 4; i++) {
            int f = tid + i * 256;           // 0..1023
            int dd = f >> 3, c = (f & 7) * 8;
            cp_async16(sb + (uint32_t)((HVOFF + buf * 128 * HVP + dd * HVP + c) * 2),
                       vp + (size_t)dd * Tt + c);
        }
    };

    // prologue: Q + K0 + V0 (one group)
    {
        const __half* qptr = g_qh + (((size_t)b * Tt + qbase) * Hh + h) * HD_;
#pragma unroll
        for (int i = 0; i < 8; i++) {
            int f = tid + i * 256;           // 0..2047
            int m = f >> 4, c = (f & 15) * 8;
            cp_async16(sb + (uint32_t)((HQOFF + m * HQP + c) * 2),
                       qptr + (size_t)m * (Hh * HD_) + c);
        }
        issue_K(0, 0);
        issue_V(0, 0);
        cp_commit();
    }

    float o[16][4];
    float mrow[2], lrow[2];
#pragma unroll
    for (int j = 0; j < 16; j++)
#pragma unroll
        for (int r = 0; r < 4; r++) o[j][r] = 0.0f;
    mrow[0] = mrow[1] = -3.0e38f;
    lrow[0] = lrow[1] = 0.0f;

    const int row0a = mw + g, row0b = mw + g + 8;
    uint32_t qa[8][4];   // Q fragments: 8 k16-steps

    const int ntiles = 2 * (qi + 1);
    for (int it = 0; it < ntiles; it++) {
        const int kbase = it * 64;
        const int bf = it & 1;

        cp_wait<0>();
        __syncthreads();

        if (it == 0) {
#pragma unroll
            for (int kk = 0; kk < 8; kk++) {
                uint32_t addr = sb + (uint32_t)((HQOFF + (mw + lrowA) * HQP
                                                 + kk * 16 + lcolA) * 2);
                ldsm_x4(qa[kk][0], qa[kk][1], qa[kk][2], qa[kk][3], addr);
            }
        }

        if (it + 1 < ntiles) {
            issue_K(it + 1, bf ^ 1);
            issue_V(it + 1, bf ^ 1);
            cp_commit();
        }

        const uint32_t kOff = (uint32_t)(HKOFF + bf * 64 * HKP);
        const uint32_t vOff = (uint32_t)(HVOFF + bf * 128 * HVP);

        // ---- S = Q @ K^T (unscaled) ----
        float s[8][4];
#pragma unroll
        for (int j = 0; j < 8; j++)
#pragma unroll
            for (int r = 0; r < 4; r++) s[j][r] = 0.0f;

#pragma unroll
        for (int kk = 0; kk < 8; kk++) {
            const int k16 = kk * 16;
#pragma unroll
            for (int j = 0; j < 8; j += 2) {
                uint32_t b00, b01, b10, b11;
                uint32_t addr = sb + (uint32_t)((kOff + (j * 8 + lrowB) * HKP
                                                 + k16 + lcolB) * 2);
                ldsm_x4(b00, b01, b10, b11, addr);
                mma_f16(s[j][0], s[j][1], s[j][2], s[j][3],
                        qa[kk][0], qa[kk][1], qa[kk][2], qa[kk][3], b00, b01);
                mma_f16(s[j + 1][0], s[j + 1][1], s[j + 1][2], s[j + 1][3],
                        qa[kk][0], qa[kk][1], qa[kk][2], qa[kk][3], b10, b11);
            }
        }

        // causal mask (unscaled scores)
        if (kbase + 63 > qbase) {
            int rga = qbase + row0a, rgb = qbase + row0b;
#pragma unroll
            for (int j = 0; j < 8; j++) {
                int cg = kbase + j * 8 + 2 * tg;
                if (cg     > rga) s[j][0] = -3.0e38f;
                if (cg + 1 > rga) s[j][1] = -3.0e38f;
                if (cg     > rgb) s[j][2] = -3.0e38f;
                if (cg + 1 > rgb) s[j][3] = -3.0e38f;
            }
        }

        // ---- online softmax (fp32, scale folded) ----
        float mx0 = -3.0e38f, mx1 = -3.0e38f;
#pragma unroll
        for (int j = 0; j < 8; j++) {
            mx0 = fmaxf(mx0, fmaxf(s[j][0], s[j][1]));
            mx1 = fmaxf(mx1, fmaxf(s[j][2], s[j][3]));
        }
        mx0 = fmaxf(mx0, __shfl_xor_sync(0xffffffffu, mx0, 1));
        mx0 = fmaxf(mx0, __shfl_xor_sync(0xffffffffu, mx0, 2));
        mx1 = fmaxf(mx1, __shfl_xor_sync(0xffffffffu, mx1, 1));
        mx1 = fmaxf(mx1, __shfl_xor_sync(0xffffffffu, mx1, 2));

        float mn0 = fmaxf(mrow[0], mx0);
        float mn1 = fmaxf(mrow[1], mx1);
        float corr0 = __expf((mrow[0] - mn0) * scale);
        float corr1 = __expf((mrow[1] - mn1) * scale);
        mrow[0] = mn0; mrow[1] = mn1;
        float c0 = mn0 * scale, c1 = mn1 * scale;

        __half* Ps = hsm + HPOFF;
        float ls0 = 0.0f, ls1 = 0.0f;
#pragma unroll
        for (int j = 0; j < 8; j++) {
            s[j][0] = __expf(fmaf(s[j][0], scale, -c0));
            s[j][1] = __expf(fmaf(s[j][1], scale, -c0));
            s[j][2] = __expf(fmaf(s[j][2], scale, -c1));
            s[j][3] = __expf(fmaf(s[j][3], scale, -c1));
            ls0 += s[j][0] + s[j][1];
            ls1 += s[j][2] + s[j][3];
            *(__half2*)(Ps + row0a * HPP + j * 8 + 2 * tg) = __floats2half2_rn(s[j][0], s[j][1]);
            *(__half2*)(Ps + row0b * HPP + j * 8 + 2 * tg) = __floats2half2_rn(s[j][2], s[j][3]);
        }
        ls0 += __shfl_xor_sync(0xffffffffu, ls0, 1);
        ls0 += __shfl_xor_sync(0xffffffffu, ls0, 2);
        ls1 += __shfl_xor_sync(0xffffffffu, ls1, 1);
        ls1 += __shfl_xor_sync(0xffffffffu, ls1, 2);
        lrow[0] = lrow[0] * corr0 + ls0;
        lrow[1] = lrow[1] * corr1 + ls1;

#pragma unroll
        for (int j = 0; j < 16; j++) {
            o[j][0] *= corr0; o[j][1] *= corr0;
            o[j][2] *= corr1; o[j][3] *= corr1;
        }

        __syncwarp();   // P strip (warp-private rows)

        // ---- O += P @ V (V transposed [d][n] in smem) ----
#pragma unroll
        for (int k16 = 0; k16 < 64; k16 += 16) {
            uint32_t a0, a1, a2, a3;
            {
                uint32_t addr = sb + (uint32_t)((HPOFF + (mw + lrowA) * HPP
                                                 + k16 + lcolA) * 2);
                ldsm_x4(a0, a1, a2, a3, addr);
            }
#pragma unroll
            for (int j = 0; j < 16; j += 2) {
                uint32_t b00, b01, b10, b11;
                uint32_t addr = sb + (uint32_t)((vOff + (j * 8 + lrowB) * HVP
                                                 + k16 + lcolB) * 2);
                ldsm_x4(b00, b01, b10, b11, addr);
                mma_f16(o[j][0], o[j][1], o[j][2], o[j][3], a0, a1, a2, a3, b00, b01);
                mma_f16(o[j + 1][0], o[j + 1][1], o[j + 1][2], o[j + 1][3],
                        a0, a1, a2, a3, b10, b11);
            }
        }
    }

    // epilogue: O /= l, write fp16 to g_yh (B,T,C) at column h*HD + d
    float inv0 = 1.0f / lrow[0], inv1 = 1.0f / lrow[1];
    size_t basea = (((size_t)b * Tt + qbase + row0a) * Cc) + (size_t)h * HD_;
    size_t baseb = (((size_t)b * Tt + qbase + row0b) * Cc) + (size_t)h * HD_;
#pragma unroll
    for (int j = 0; j < 16; j++) {
        int col = j * 8 + 2 * tg;
        *(__half2*)(g_yh + basea + col) = __floats2half2_rn(o[j][0] * inv0, o[j][1] * inv0);
        *(__half2*)(g_yh + baseb + col) = __floats2half2_rn(o[j][2] * inv1, o[j][3] * inv1);
    }
}

// ---------------------------------------------------------------------------
// Launch
// ---------------------------------------------------------------------------
extern "C" void kernel_launch(void* const* d_in, const int* in_sizes, int n_in,
                              void* d_out, int out_size)
{
    const float* x    = (const float*)d_in[0];
    const float* cosp = (const float*)d_in[1];
    const float* sinp = (const float*)d_in[2];
    const float* wq   = (const float*)d_in[3];
    const float* wk   = (const float*)d_in[4];
    const float* wv   = (const float*)d_in[5];
    const float* wo   = (const float*)d_in[6];
    const float* qkw  = (const float*)d_in[7];
    float* out = (float*)d_out;

    // 0. convert x -> fp16; weights -> transposed fp16
    {
        const int thr = 256;
        round_x_kernel<<<(BT * Cc / 4 + thr - 1) / thr, thr>>>(x, BT * Cc / 4);
        dim3 tb(32, 8);
        round_t_kernel<1><<<dim3(Cc / 32, Cc / 32), tb>>>(wq, Cc, Cc);
        round_t_kernel<2><<<dim3((KVH_ * HD_) / 32, Cc / 32), tb>>>(wk, Cc, KVH_ * HD_);
        round_t_kernel<3><<<dim3((KVH_ * HD_) / 32, Cc / 32), tb>>>(wv, Cc, KVH_ * HD_);
        round_t_kernel<4><<<dim3(Cc / 32, Cc / 32), tb>>>(wo, Cc, Cc);
    }

    // 1. QKV projections (fp16 tensor cores + LDSM)
    f16_gemm<0><<<dim3(Cc / 128, GM / 128), 256>>>(nullptr);
    f16_gemm<1><<<dim3((KVH_ * HD_) / 128, GM / 128), 256>>>(nullptr);
    f16_gemm<2><<<dim3((KVH_ * HD_) / 128, GM / 128), 256>>>(nullptr);

    // 2. RoPE + RMSNorm (fp32 in, fp16 out)
    {
        int total_warps = BT * Hh + BT * KVH_;
        int threads = 256;
        int blocks = (total_warps * 32 + threads - 1) / threads;
        rope_rmsnorm_kernel<<<blocks, threads>>>(cosp, sinp, qkw);
    }

    // 3. flash attention (fp16 m16n8k16 + LDSM, ~125 KB smem)
    {
        size_t smem_bytes = FA_SMEM_HALFS * sizeof(__half);
        cudaFuncSetAttribute(flash_attn_f16,
                             cudaFuncAttributeMaxDynamicSharedMemorySize,
                             (int)smem_bytes);
        flash_attn_f16<<<dim3(Tt / 128, Hh, Bb), 256, smem_bytes>>>();
    }

    // 4. output projection (fp16 tensor cores + LDSM, fp32 out)
    f16_gemm<3><<<dim3(Cc / 128, GM / 128), 256>>>(out);
}

// round 16
// speedup vs baseline: 5.7398x; 1.0037x over previous
#include <cuda_runtime.h>
#include <cuda_fp16.h>
#include <cstdint>

// Problem constants
#define Bb   2
#define Tt   2048
#define Cc   2048
#define Hh   16
#define KVH_ 4
#define HD_  128
#define BT   (Bb*Tt)          // 4096
#define REP  (Hh/KVH_)        // 4

// Scratch buffers (device globals).
__device__ float  g_q[BT * Hh * HD_];      // fp32 QKV projections (pre-rope)
__device__ float  g_k[BT * KVH_ * HD_];
__device__ __half g_xh[BT * Cc];           // fp16 x
__device__ __half g_wq_h[Cc * Cc];         // fp16 weights, TRANSPOSED [N][K]
__device__ __half g_wk_h[Cc * KVH_ * HD_];
__device__ __half g_wv_h[Cc * KVH_ * HD_];
__device__ __half g_wo_h[Cc * Cc];
__device__ __half g_qh[BT * Hh * HD_];     // fp16 q/k after rope+rmsnorm
__device__ __half g_kh[BT * KVH_ * HD_];
__device__ __half g_vt[(size_t)Bb * KVH_ * HD_ * Tt];  // fp16 V TRANSPOSED [b][kvh][d][T]
__device__ __half g_yh[BT * Cc];           // fp16 attention output

// ---------------------------------------------------------------------------
// ldmatrix x4: four 8x8 b16 tiles -> 4 b32 fragment regs.
// ---------------------------------------------------------------------------
__device__ __forceinline__ void ldsm_x4(uint32_t& r0, uint32_t& r1,
                                        uint32_t& r2, uint32_t& r3,
                                        uint32_t saddr)
{
    asm volatile("ldmatrix.sync.aligned.m8n8.x4.shared.b16 {%0,%1,%2,%3}, [%4];"
                 : "=r"(r0), "=r"(r1), "=r"(r2), "=r"(r3) : "r"(saddr));
}

// ---------------------------------------------------------------------------
// Pre-pass: x fp32 -> fp16
// ---------------------------------------------------------------------------
__global__ void round_x_kernel(const float* __restrict__ src, int n4)
{
    int i = blockIdx.x * blockDim.x + threadIdx.x;
    if (i >= n4) return;
    float4 v = ((const float4*)src)[i];
    __half2* d = (__half2*)(g_xh + (size_t)i * 4);
    d[0] = __floats2half2_rn(v.x, v.y);
    d[1] = __floats2half2_rn(v.z, v.w);
}

// ---------------------------------------------------------------------------
// Pre-pass: weight [K][N] fp32 -> [N][K] fp16 (transpose).
// ---------------------------------------------------------------------------
template<int R>
__global__ void round_t_kernel(const float* __restrict__ src, int K, int N)
{
    __half* dst;
    if      (R == 1) dst = g_wq_h;
    else if (R == 2) dst = g_wk_h;
    else if (R == 3) dst = g_wv_h;
    else             dst = g_wo_h;
    __shared__ float tile[32][33];
    int n0 = blockIdx.x * 32, k0 = blockIdx.y * 32;
    int tx = threadIdx.x, ty = threadIdx.y;
#pragma unroll
    for (int i = 0; i < 4; i++)
        tile[ty + i * 8][tx] = src[(size_t)(k0 + ty + i * 8) * N + n0 + tx];
    __syncthreads();
#pragma unroll
    for (int i = 0; i < 4; i++)
        dst[(size_t)(n0 + ty + i * 8) * K + k0 + tx] = __float2half_rn(tile[tx][ty + i * 8]);
}

// ---------------------------------------------------------------------------
// fp16 mma m16n8k16, fp32 accumulate (R14-verified layouts).
// ---------------------------------------------------------------------------
__device__ __forceinline__ void mma_f16(
    float& d0, float& d1, float& d2, float& d3,
    uint32_t a0, uint32_t a1, uint32_t a2, uint32_t a3,
    uint32_t b0, uint32_t b1)
{
    asm volatile(
        "mma.sync.aligned.m16n8k16.row.col.f32.f16.f16.f32 "
        "{%0,%1,%2,%3}, {%4,%5,%6,%7}, {%8,%9}, {%0,%1,%2,%3};\n"
        : "+f"(d0), "+f"(d1), "+f"(d2), "+f"(d3)
        : "r"(a0), "r"(a1), "r"(a2), "r"(a3), "r"(b0), "r"(b1));
}

__device__ __forceinline__ void cp_async16(uint32_t smem_addr, const void* gptr) {
    asm volatile("cp.async.cg.shared.global [%0], [%1], 16;\n"
                 :: "r"(smem_addr), "l"(gptr));
}
__device__ __forceinline__ void cp_commit() {
    asm volatile("cp.async.commit_group;\n");
}
template<int N>
__device__ __forceinline__ void cp_wait() {
    asm volatile("cp.async.wait_group %0;\n" :: "n"(N));
}

// ---------------------------------------------------------------------------
// fp16 tensor-core GEMM with LDSM fragment loads.
// Tile 128x128, BK=32, 256 threads (2x4 warps, 64x32/warp), double-buffered.
// OP: 0=q->g_q(f32), 1=k->g_k(f32), 2=v->g_vt(f16 transposed), 3=out(f32).
// ---------------------------------------------------------------------------
#define GK 2048
#define GM 4096
#define HP 40    // smem pitch in halfs (80B rows; LDSM rows hit banks 20r mod 32)

template<int OP>
__global__ void __launch_bounds__(256) f16_gemm(float* __restrict__ Cext)
{
    constexpr int N = (OP == 1 || OP == 2) ? (KVH_ * HD_) : Cc;
    const __half* A = (OP == 3) ? g_yh : g_xh;
    const __half* Bt;
    if      (OP == 0) Bt = g_wq_h;
    else if (OP == 1) Bt = g_wk_h;
    else if (OP == 2) Bt = g_wv_h;
    else              Bt = g_wo_h;

    __shared__ __half As[2][128][HP];
    __shared__ __half Bs[2][128][HP];

    const int tid  = threadIdx.x;
    const int wid  = tid >> 5;
    const int lane = tid & 31;
    const int g    = lane >> 2;
    const int tg   = lane & 3;
    const int mbase = (wid >> 2) * 64;
    const int nbase = (wid & 3) * 32;
    const int bm = blockIdx.y * 128, bn = blockIdx.x * 128;

    // LDSM lane-address offsets:
    // A-pattern: matrices (row+0 lo, row+8 lo, row+0 hi, row+8 hi)
    const int lrowA = (lane & 7) + ((lane >> 3) & 1) * 8;   // row offset within 16
    const int lcolA = (lane >> 4) * 8;                      // k offset 0/8
    // B-pattern: matrices (blk j lo, j hi, j+1 lo, j+1 hi)
    const int lrowB = ((lane >> 4) & 1) * 8 + (lane & 7);   // row offset within 16 (j..j+1)
    const int lcolB = ((lane >> 3) & 1) * 8;                // k offset 0/8

    float d[4][4][4];
#pragma unroll
    for (int i = 0; i < 4; i++)
#pragma unroll
        for (int j = 0; j < 4; j++)
#pragma unroll
            for (int r = 0; r < 4; r++) d[i][j][r] = 0.0f;

    uint32_t sbA = (uint32_t)__cvta_generic_to_shared(&As[0][0][0]);
    uint32_t sbB = (uint32_t)__cvta_generic_to_shared(&Bs[0][0][0]);

    auto issue_stage = [&](int k0, int buf) {
#pragma unroll
        for (int i = 0; i < 2; i++) {
            int f   = tid + i * 256;        // 0..511
            int row = f >> 2;
            int c   = (f & 3) * 8;          // halfs
            cp_async16(sbA + (uint32_t)((buf * 128 * HP + row * HP + c) * 2),
                       A + (size_t)(bm + row) * GK + k0 + c);
        }
#pragma unroll
        for (int i = 0; i < 2; i++) {
            int f   = tid + i * 256;
            int row = f >> 2;
            int c   = (f & 3) * 8;
            cp_async16(sbB + (uint32_t)((buf * 128 * HP + row * HP + c) * 2),
                       Bt + (size_t)(bn + row) * GK + k0 + c);
        }
        cp_commit();
    };

    constexpr int NITER = GK / 32;
    issue_stage(0, 0);

    for (int it = 0; it < NITER; it++) {
        const int bf = it & 1;
        if (it + 1 < NITER) {
            issue_stage((it + 1) * 32, (it + 1) & 1);
            cp_wait<1>();
        } else {
            cp_wait<0>();
        }
        __syncthreads();

#pragma unroll
        for (int kc = 0; kc < 2; kc++) {
            const int k16 = kc * 16;
            uint32_t a[4][4], b[4][2];
#pragma unroll
            for (int mt = 0; mt < 4; mt++) {
                uint32_t addr = (uint32_t)__cvta_generic_to_shared(
                    &As[bf][mbase + mt * 16 + lrowA][k16 + lcolA]);
                ldsm_x4(a[mt][0], a[mt][1], a[mt][2], a[mt][3], addr);
            }
#pragma unroll
            for (int nt = 0; nt < 4; nt += 2) {
                uint32_t addr = (uint32_t)__cvta_generic_to_shared(
                    &Bs[bf][nbase + nt * 8 + lrowB][k16 + lcolB]);
                ldsm_x4(b[nt][0], b[nt][1], b[nt + 1][0], b[nt + 1][1], addr);
            }
#pragma unroll
            for (int mt = 0; mt < 4; mt++)
#pragma unroll
                for (int nt = 0; nt < 4; nt++)
                    mma_f16(d[mt][nt][0], d[mt][nt][1], d[mt][nt][2], d[mt][nt][3],
                            a[mt][0], a[mt][1], a[mt][2], a[mt][3],
                            b[nt][0], b[nt][1]);
        }
        __syncthreads();
    }

    // epilogue
#pragma unroll
    for (int mt = 0; mt < 4; mt++) {
        int row = bm + mbase + mt * 16 + g;
#pragma unroll
        for (int nt = 0; nt < 4; nt++) {
            int col = bn + nbase + nt * 8 + 2 * tg;
            if (OP == 0) {
                *(float2*)(g_q + (size_t)row * N + col)       = make_float2(d[mt][nt][0], d[mt][nt][1]);
                *(float2*)(g_q + (size_t)(row + 8) * N + col) = make_float2(d[mt][nt][2], d[mt][nt][3]);
            } else if (OP == 1) {
                *(float2*)(g_k + (size_t)row * N + col)       = make_float2(d[mt][nt][0], d[mt][nt][1]);
                *(float2*)(g_k + (size_t)(row + 8) * N + col) = make_float2(d[mt][nt][2], d[mt][nt][3]);
            } else if (OP == 2) {
                // V: store transposed fp16 into g_vt[b][kvh][dd][T]
#pragma unroll
                for (int rr = 0; rr < 2; rr++) {
                    int r2 = row + rr * 8;
                    int bI = r2 / Tt, t = r2 % Tt;
#pragma unroll
                    for (int cc = 0; cc < 2; cc++) {
                        int c2 = col + cc;
                        int kvh = c2 / HD_, dd = c2 % HD_;
                        g_vt[(((size_t)bI * KVH_ + kvh) * HD_ + dd) * Tt + t] =
                            __float2half_rn(d[mt][nt][rr * 2 + cc]);
                    }
                }
            } else {
                *(float2*)(Cext + (size_t)row * N + col)       = make_float2(d[mt][nt][0], d[mt][nt][1]);
                *(float2*)(Cext + (size_t)(row + 8) * N + col) = make_float2(d[mt][nt][2], d[mt][nt][3]);
            }
        }
    }
}

// ---------------------------------------------------------------------------
// RoPE + RMSNorm, one warp per row of 128. Reads fp32, writes fp16.
// ---------------------------------------------------------------------------
__global__ void rope_rmsnorm_kernel(const float* __restrict__ cosp,
                                    const float* __restrict__ sinp,
                                    const float* __restrict__ qk_w)
{
    const int QROWS = BT * Hh;
    const int KROWS = BT * KVH_;
    int warp = (blockIdx.x * blockDim.x + threadIdx.x) >> 5;
    int lane = threadIdx.x & 31;
    const float* row;
    __half* dst;
    int t;
    if (warp < QROWS) {
        t = (warp / Hh) % Tt;
        row = g_q + (size_t)warp * HD_;
        dst = g_qh + (size_t)warp * HD_;
    } else {
        int w = warp - QROWS;
        if (w >= KROWS) return;
        t = (w / KVH_) % Tt;
        row = g_k + (size_t)w * HD_;
        dst = g_kh + (size_t)w * HD_;
    }
    int j0 = lane, j1 = lane + 32;
    float x1a = row[j0],      x1b = row[j1];
    float x2a = row[j0 + 64], x2b = row[j1 + 64];
    float ca = cosp[t * 64 + j0], sa = sinp[t * 64 + j0];
    float cb = cosp[t * 64 + j1], sb = sinp[t * 64 + j1];
    float o1a = x1a * ca - x2a * sa, o2a = x2a * ca + x1a * sa;
    float o1b = x1b * cb - x2b * sb, o2b = x2b * cb + x1b * sb;
    float ss = o1a * o1a + o2a * o2a + o1b * o1b + o2b * o2b;
#pragma unroll
    for (int off = 16; off; off >>= 1) ss += __shfl_xor_sync(0xffffffffu, ss, off);
    float rms = rsqrtf(ss * (1.0f / 128.0f) + 1e-6f);
    dst[j0]      = __float2half_rn(o1a * rms * qk_w[j0]);
    dst[j1]      = __float2half_rn(o1b * rms * qk_w[j1]);
    dst[j0 + 64] = __float2half_rn(o2a * rms * qk_w[j0 + 64]);
    dst[j1 + 64] = __float2half_rn(o2b * rms * qk_w[j1 + 64]);
}

// ---------------------------------------------------------------------------
// Flash attention, fp16 m16n8k16 + LDSM fragment loads.
// BM=128, BN=64, D=128, 256 threads, 8 warps x 16 rows.
// Q frags cached in regs; K double-buffered [n][d]; V double-buffered
// TRANSPOSED [d][n]; P fp16 [m][n]. Softmax fp32, scale folded.
// Pitches (halfs): Q/K 136, V/P 72. Smem = 124928 B.
// ---------------------------------------------------------------------------
#define HQP 136
#define HKP 136
#define HVP 72
#define HPP 72
#define HQOFF 0
#define HKOFF (128 * HQP)                       // 17408
#define HVOFF (HKOFF + 2 * 64 * HKP)            // 34816
#define HPOFF (HVOFF + 2 * 128 * HVP)           // 53248
#define FA_SMEM_HALFS (HPOFF + 128 * HPP)       // 62464 halfs = 124928 B

__global__ void __launch_bounds__(256, 1) flash_attn_f16()
{
    extern __shared__ __half hsm[];

    const int qi = (int)gridDim.x - 1 - (int)blockIdx.x;   // heavy blocks first
    const int h = blockIdx.y, b = blockIdx.z;
    const int kvh = h / REP;
    const int tid = threadIdx.x;
    const int wid = tid >> 5, lane = tid & 31;
    const int g = lane >> 2, tg = lane & 3;
    const int mw = wid * 16;
    const int qbase = qi * 128;
    const float scale = 0.08838834764831845f;   // 1/sqrt(128)

    uint32_t sb = (uint32_t)__cvta_generic_to_shared(hsm);

    // LDSM lane-address offsets (same mapping as GEMM)
    const int lrowA = (lane & 7) + ((lane >> 3) & 1) * 8;
    const int lcolA = (lane >> 4) * 8;
    const int lrowB = ((lane >> 4) & 1) * 8 + (lane & 7);
    const int lcolB = ((lane >> 3) & 1) * 8;

    auto issue_K = [&](int t, int buf) {
        const __half* kp = g_kh + (((size_t)b * Tt + t * 64) * KVH_ + kvh) * HD_;
#pragma unroll
        for (int i = 0; i < 4; i++) {
            int f = tid + i * 256;           // 0..1023
            int n = f >> 4, c = (f & 15) * 8;
            cp_async16(sb + (uint32_t)((HKOFF + buf * 64 * HKP + n * HKP + c) * 2),
                       kp + (size_t)n * (KVH_ * HD_) + c);
        }
    };
    auto issue_V = [&](int t, int buf) {
        const __half* vp = g_vt + (((size_t)b * KVH_ + kvh) * HD_) * Tt + (size_t)t * 64;
#pragma unroll
        for (int i = 0; i < 4; i++) {
            int f = tid + i * 256;           // 0..1023
            int dd = f >> 3, c = (f & 7) * 8;
            cp_async16(sb + (uint32_t)((HVOFF + buf * 128 * HVP + dd * HVP + c) * 2),
                       vp + (size_t)dd * Tt + c);
        }
    };

    // prologue: Q + K0 + V0 (one group)
    {
        const __half* qptr = g_qh + (((size_t)b * Tt + qbase) * Hh + h) * HD_;
#pragma unroll
        for (int i = 0; i < 8; i++) {
            int f = tid + i * 256;           // 0..2047
            int m = f >> 4, c = (f & 15) * 8;
            cp_async16(sb + (uint32_t)((HQOFF + m * HQP + c) * 2),
                       qptr + (size_t)m * (Hh * HD_) + c);
        }
        issue_K(0, 0);
        issue_V(0, 0);
        cp_commit();
    }

    float o[16][4];
    float mrow[2], lrow[2];
#pragma unroll
    for (int j = 0; j < 16; j++)
#pragma unroll
        for (int r = 0; r < 4; r++) o[j][r] = 0.0f;
    mrow[0] = mrow[1] = -3.0e38f;
    lrow[0] = lrow[1] = 0.0f;

    const int row0a = mw + g, row0b = mw + g + 8;
    uint32_t qa[8][4];   // Q fragments: 8 k16-steps

    const int ntiles = 2 * (qi + 1);
    for (int it = 0; it < ntiles; it++) {
        const int kbase = it * 64;
        const int bf = it & 1;

        cp_wait<0>();
        __syncthreads();

        if (it == 0) {
#pragma unroll
            for (int kk = 0; kk < 8; kk++) {
                uint32_t addr = sb + (uint32_t)((HQOFF + (mw + lrowA) * HQP
                                                 + kk * 16 + lcolA) * 2);
                ldsm_x4(qa[kk][0], qa[kk][1], qa[kk][2], qa[kk][3], addr);
            }
        }

        if (it + 1 < ntiles) {
            issue_K(it + 1, bf ^ 1);
            issue_V(it + 1, bf ^ 1);
            cp_commit();
        }

        const uint32_t kOff = (uint32_t)(HKOFF + bf * 64 * HKP);
        const uint32_t vOff = (uint32_t)(HVOFF + bf * 128 * HVP);

        // ---- S = Q @ K^T (unscaled) ----
        float s[8][4];
#pragma unroll
        for (int j = 0; j < 8; j++)
#pragma unroll
            for (int r = 0; r < 4; r++) s[j][r] = 0.0f;

#pragma unroll
        for (int kk = 0; kk < 8; kk++) {
            const int k16 = kk * 16;
#pragma unroll
            for (int j = 0; j < 8; j += 2) {
                uint32_t b00, b01, b10, b11;
                uint32_t addr = sb + (uint32_t)((kOff + (j * 8 + lrowB) * HKP
                                                 + k16 + lcolB) * 2);
                ldsm_x4(b00, b01, b10, b11, addr);
                mma_f16(s[j][0], s[j][1], s[j][2], s[j][3],
                        qa[kk][0], qa[kk][1], qa[kk][2], qa[kk][3], b00, b01);
                mma_f16(s[j + 1][0], s[j + 1][1], s[j + 1][2], s[j + 1][3],
                        qa[kk][0], qa[kk][1], qa[kk][2], qa[kk][3], b10, b11);
            }
        }

        // causal mask (unscaled scores)
        if (kbase + 63 > qbase) {
            int rga = qbase + row0a, rgb = qbase + row0b;
#pragma unroll
            for (int j = 0; j < 8; j++) {
                int cg = kbase + j * 8 + 2 * tg;
                if (cg     > rga) s[j][0] = -3.0e38f;
                if (cg + 1 > rga) s[j][1] = -3.0e38f;
                if (cg     > rgb) s[j][2] = -3.0e38f;
                if (cg + 1 > rgb) s[j][3] = -3.0e38f;
            }
        }

        // ---- online softmax (fp32, scale folded) ----
        float mx0 = -3.0e38f, mx1 = -3.0e38f;
#pragma unroll
        for (int j = 0; j < 8; j++) {
            mx0 = fmaxf(mx0, fmaxf(s[j][0], s[j][1]));
            mx1 = fmaxf(mx1, fmaxf(s[j][2], s[j][3]));
        }
        mx0 = fmaxf(mx0, __shfl_xor_sync(0xffffffffu, mx0, 1));
        mx0 = fmaxf(mx0, __shfl_xor_sync(0xffffffffu, mx0, 2));
        mx1 = fmaxf(mx1, __shfl_xor_sync(0xffffffffu, mx1, 1));
        mx1 = fmaxf(mx1, __shfl_xor_sync(0xffffffffu, mx1, 2));

        float mn0 = fmaxf(mrow[0], mx0);
        float mn1 = fmaxf(mrow[1], mx1);
        float corr0 = __expf((mrow[0] - mn0) * scale);
        float corr1 = __expf((mrow[1] - mn1) * scale);
        mrow[0] = mn0; mrow[1] = mn1;
        float c0 = mn0 * scale, c1 = mn1 * scale;

        __half* Ps = hsm + HPOFF;
        float ls0 = 0.0f, ls1 = 0.0f;
#pragma unroll
        for (int j = 0; j < 8; j++) {
            s[j][0] = __expf(fmaf(s[j][0], scale, -c0));
            s[j][1] = __expf(fmaf(s[j][1], scale, -c0));
            s[j][2] = __expf(fmaf(s[j][2], scale, -c1));
            s[j][3] = __expf(fmaf(s[j][3], scale, -c1));
            ls0 += s[j][0] + s[j][1];
            ls1 += s[j][2] + s[j][3];
            *(__half2*)(Ps + row0a * HPP + j * 8 + 2 * tg) = __floats2half2_rn(s[j][0], s[j][1]);
            *(__half2*)(Ps + row0b * HPP + j * 8 + 2 * tg) = __floats2half2_rn(s[j][2], s[j][3]);
        }
        ls0 += __shfl_xor_sync(0xffffffffu, ls0, 1);
        ls0 += __shfl_xor_sync(0xffffffffu, ls0, 2);
        ls1 += __shfl_xor_sync(0xffffffffu, ls1, 1);
        ls1 += __shfl_xor_sync(0xffffffffu, ls1, 2);
        lrow[0] = lrow[0] * corr0 + ls0;
        lrow[1] = lrow[1] * corr1 + ls1;

#pragma unroll
        for (int j = 0; j < 16; j++) {
            o[j][0] *= corr0; o[j][1] *= corr0;
            o[j][2] *= corr1; o[j][3] *= corr1;
        }

        __syncwarp();   // P strip (warp-private rows)

        // ---- O += P @ V (V transposed [d][n] in smem) ----
#pragma unroll
        for (int k16 = 0; k16 < 64; k16 += 16) {
            uint32_t a0, a1, a2, a3;
            {
                uint32_t addr = sb + (uint32_t)((HPOFF + (mw + lrowA) * HPP
                                                 + k16 + lcolA) * 2);
                ldsm_x4(a0, a1, a2, a3, addr);
            }
#pragma unroll
            for (int j = 0; j < 16; j += 2) {
                uint32_t b00, b01, b10, b11;
                uint32_t addr = sb + (uint32_t)((vOff + (j * 8 + lrowB) * HVP
                                                 + k16 + lcolB) * 2);
                ldsm_x4(b00, b01, b10, b11, addr);
                mma_f16(o[j][0], o[j][1], o[j][2], o[j][3], a0, a1, a2, a3, b00, b01);
                mma_f16(o[j + 1][0], o[j + 1][1], o[j + 1][2], o[j + 1][3],
                        a0, a1, a2, a3, b10, b11);
            }
        }
    }

    // epilogue: O /= l, write fp16 to g_yh (B,T,C) at column h*HD + d
    float inv0 = 1.0f / lrow[0], inv1 = 1.0f / lrow[1];
    size_t basea = (((size_t)b * Tt + qbase + row0a) * Cc) + (size_t)h * HD_;
    size_t baseb = (((size_t)b * Tt + qbase + row0b) * Cc) + (size_t)h * HD_;
#pragma unroll
    for (int j = 0; j < 16; j++) {
        int col = j * 8 + 2 * tg;
        *(__half2*)(g_yh + basea + col) = __floats2half2_rn(o[j][0] * inv0, o[j][1] * inv0);
        *(__half2*)(g_yh + baseb + col) = __floats2half2_rn(o[j][2] * inv1, o[j][3] * inv1);
    }
}

// ---------------------------------------------------------------------------
// Launch
// ---------------------------------------------------------------------------
extern "C" void kernel_launch(void* const* d_in, const int* in_sizes, int n_in,
                              void* d_out, int out_size)
{
    const float* x    = (const float*)d_in[0];
    const float* cosp = (const float*)d_in[1];
    const float* sinp = (const float*)d_in[2];
    const float* wq   = (const float*)d_in[3];
    const float* wk   = (const float*)d_in[4];
    const float* wv   = (const float*)d_in[5];
    const float* wo   = (const float*)d_in[6];
    const float* qkw  = (const float*)d_in[7];
    float* out = (float*)d_out;

    // 0. convert x -> fp16; weights -> transposed fp16
    {
        const int thr = 256;
        round_x_kernel<<<(BT * Cc / 4 + thr - 1) / thr, thr>>>(x, BT * Cc / 4);
        dim3 tb(32, 8);
        round_t_kernel<1><<<dim3(Cc / 32, Cc / 32), tb>>>(wq, Cc, Cc);
        round_t_kernel<2><<<dim3((KVH_ * HD_) / 32, Cc / 32), tb>>>(wk, Cc, KVH_ * HD_);
        round_t_kernel<3><<<dim3((KVH_ * HD_) / 32, Cc / 32), tb>>>(wv, Cc, KVH_ * HD_);
        round_t_kernel<4><<<dim3(Cc / 32, Cc / 32), tb>>>(wo, Cc, Cc);
    }

    // 1. QKV projections (fp16 tensor cores + LDSM)
    f16_gemm<0><<<dim3(Cc / 128, GM / 128), 256>>>(nullptr);
    f16_gemm<1><<<dim3((KVH_ * HD_) / 128, GM / 128), 256>>>(nullptr);
    f16_gemm<2><<<dim3((KVH_ * HD_) / 128, GM / 128), 256>>>(nullptr);

    // 2. RoPE + RMSNorm (fp32 in, fp16 out)
    {
        int total_warps = BT * Hh + BT * KVH_;
        int threads = 256;
        int blocks = (total_warps * 32 + threads - 1) / threads;
        rope_rmsnorm_kernel<<<blocks, threads>>>(cosp, sinp, qkw);
    }

    // 3. flash attention (fp16 m16n8k16 + LDSM, ~125 KB smem)
    {
        size_t smem_bytes = FA_SMEM_HALFS * sizeof(__half);
        cudaFuncSetAttribute(flash_attn_f16,
                             cudaFuncAttributeMaxDynamicSharedMemorySize,
                             (int)smem_bytes);
        flash_attn_f16<<<dim3(Tt / 128, Hh, Bb), 256, smem_bytes>>>();
    }

    // 4. output projection (fp16 tensor cores + LDSM, fp32 out)
    f16_gemm<3><<<dim3(Cc / 128, GM / 128), 256>>>(out);
}